// round 14
// baseline (speedup 1.0000x reference)
#include <cuda_runtime.h>
#include <cuda_fp16.h>
#include <mma.h>
#include <cstdint>

using namespace nvcuda;

// Problem constants
#define Bb 8
#define Cc 64
#define Nn 500
#define Tt 12
#define Hh 4
#define Ff 64
#define Ss (Bb * Tt)   // 96 slices (b,t)
#define HF (Hh * Ff)   // 256
#define MAXD 128
#define ROWPAD 16
#define ALPHAc 0.05f
#define LEAKc 0.2f

// ---------------- scratch (device globals; no allocation) ----------------
__device__ float   g_xT[Ss * Nn * Cc];                   // [s,n,c] fp32 (final path)
__device__ __half  g_xT16[Ss * Nn * Cc];                 // fp16 iterates
__device__ __half  g_h1T16[Ss * Nn * Cc];
__device__ __half  g_h2T16[Ss * Nn * Cc];
__device__ __half  g_Wh16[(size_t)Ss * Nn * HF];         // [s,n,hf] fp16
__device__ __half  g_hpr16[((size_t)Ss * Nn + ROWPAD) * HF]; // padded for OOB frag rows
__device__ float   g_e1v[Ss * Nn * 4];                   // [(s*N+n)*4 + h]
__device__ float   g_e2v[Ss * Nn * 4];
__device__ __half  g_Wcat16[Cc * HF];                    // [c, h*F+f] fp16
__device__ __half  g_WgT16[HF * Cc];                     // [hf, o] fp16
__device__ float   g_WmT[3 * Cc * Cc];                   // [c_global, o]
__device__ int     g_cnt[Nn];
__device__ int     g_nbr[Nn * MAXD];

// ================= merged prep: nbr list + weight layouts + input transpose =========
__global__ void prep_all(const float* __restrict__ adj,
                         const float* __restrict__ W,
                         const float* __restrict__ Wg,
                         const float* __restrict__ Wm,
                         const float* __restrict__ x,
                         float* __restrict__ xT) {
    __shared__ float sm[16][193];
    const int blk = blockIdx.x;
    if (blk < 125) {
        if (threadIdx.x >= 128) return;
        int warp = threadIdx.x >> 5;
        int lane = threadIdx.x & 31;
        int n = blk * 4 + warp;
        if (n >= Nn) return;
        int base = 0;
        for (int m0 = 0; m0 < 512; m0 += 32) {
            int m = m0 + lane;
            bool p = (m < Nn) && (adj[n * Nn + m] > 0.f || m == n);
            unsigned mask = __ballot_sync(0xffffffffu, p);
            if (p) {
                int r = __popc(mask & ((1u << lane) - 1));
                if (base + r < MAXD) g_nbr[n * MAXD + base + r] = m;
            }
            base += __popc(mask);
        }
        if (lane == 0) g_cnt[n] = base < MAXD ? base : MAXD;
    } else if (blk < 189) {
        int i = (blk - 125) * 256 + threadIdx.x;
        if (i < Hh * Cc * Ff) {  // Wcat16[c, h*F+f] = W[h,c,f]
            int f = i % Ff; int rest = i / Ff;
            int c = rest % Cc; int h = rest / Cc;
            g_Wcat16[c * HF + h * Ff + f] = __float2half_rn(W[(h * Cc + c) * Ff + f]);
        }
        if (i < HF * Cc) {       // WgT16[hf, o] = half(Wg[o, hf])
            int o = i % Cc; int hf = i / Cc;
            g_WgT16[hf * Cc + o] = __float2half_rn(Wg[o * HF + hf]);
        }
        if (i < 3 * Cc * Cc) {   // WmT[c, o] = Wm[o, c]
            int o = i % Cc; int c = i / Cc;
            g_WmT[c * Cc + o] = Wm[o * (3 * Cc) + c];
        }
    } else {
        // transpose: x[b,c,n,t] -> xT[s,n,c] (fp32 + fp16)
        if (threadIdx.x >= 192) return;
        const int bi = blk - 189;
        const int nb = bi & 31, cb = (bi >> 5) & 3, b = bi >> 7;
        const int c0 = cb * 16, n0 = nb * 16;
        const int tt_ = threadIdx.x;
        const int ni_l = tt_ / 12, tl = tt_ % 12;
        const int n_l = n0 + ni_l;
        #pragma unroll
        for (int ci = 0; ci < 16; ++ci) {
            float v = 0.f;
            if (n_l < Nn)
                v = x[(((size_t)b * Cc + c0 + ci) * Nn + n_l) * Tt + tl];
            sm[ci][tt_] = v;
        }
        __syncthreads();
        #pragma unroll
        for (int rep = 0; rep < 16; ++rep) {
            int idx = rep * 192 + tt_;
            int ci = idx & 15;
            int rest = idx >> 4;
            int ni = rest / 12, t = rest % 12;
            int n = n0 + ni;
            if (n < Nn) {
                size_t oi = (((size_t)(b * Tt + t) * Nn) + n) * Cc + c0 + ci;
                float v = sm[ci][rest];
                xT[oi] = v;
                g_xT16[oi] = __float2half_rn(v);
            }
        }
    }
}

// ================= fp16 HMMA projection GEMM (2 heads/block) + e-vec + fp16 Wh ======
// grid (Ss, 8, 2), block 256 (8 warps). Tile 64 rows x 128 cols (heads 2z, 2z+1), K=64.
#define PAS_LD 72
#define PBS_LD 136
#define PCS_LD 132
__global__ void gemm_proj16(const __half* __restrict__ Ain,
                            const float* __restrict__ a1,
                            const float* __restrict__ a2) {
    __shared__ __align__(16) char smemRaw[64 * PCS_LD * 4];      // 33792 B
    __half (*As)[PAS_LD] = (__half(*)[PAS_LD])smemRaw;           // 9216 B
    __half (*Bs)[PBS_LD] = (__half(*)[PBS_LD])(smemRaw + 64 * PAS_LD * 2); // 17408 B
    float (*Cs)[PCS_LD] = (float(*)[PCS_LD])smemRaw;             // reuse after MMA

    const int s = blockIdx.x;
    const int r0 = blockIdx.y * 64;
    const int z = blockIdx.z;            // head pair
    const int c0 = z * 128;
    const int tid = threadIdx.x;
    const int wid = tid >> 5;
    const int wm = wid & 3, wn = wid >> 2;   // rows wm*16, cols wn*64
    const size_t rowB = (size_t)s * Nn;

    // stage A: 64 rows x 64 halfs (8 uint4/row), 2 uint4/thread
    {
        const uint4* srcA = (const uint4*)(Ain + rowB * Cc);
        #pragma unroll
        for (int k = 0; k < 2; ++k) {
            int idx = k * 256 + tid;
            int r = idx >> 3, p = idx & 7;
            int row = r0 + r;
            uint4 v = make_uint4(0, 0, 0, 0);
            if (row < Nn) v = srcA[(size_t)row * 8 + p];
            *(uint4*)&As[r][p * 8] = v;
        }
    }
    // stage B: Wcat16 rows 0..63, cols c0..c0+127 (16 uint4/row), 4 uint4/thread
    {
        const uint4* srcB = (const uint4*)(g_Wcat16 + c0);
        #pragma unroll
        for (int k = 0; k < 4; ++k) {
            int idx = k * 256 + tid;
            int r = idx >> 4, p = idx & 15;
            *(uint4*)&Bs[r][p * 8] = srcB[r * 32 + p];   // row stride 256 half = 32 uint4
        }
    }
    __syncthreads();

    wmma::fragment<wmma::accumulator, 16, 16, 16, float> fc[4];
    #pragma unroll
    for (int j = 0; j < 4; ++j) wmma::fill_fragment(fc[j], 0.f);
    #pragma unroll
    for (int k0 = 0; k0 < 64; k0 += 16) {
        wmma::fragment<wmma::matrix_a, 16, 16, 16, __half, wmma::row_major> fa;
        wmma::load_matrix_sync(fa, &As[wm * 16][k0], PAS_LD);
        #pragma unroll
        for (int j = 0; j < 4; ++j) {
            wmma::fragment<wmma::matrix_b, 16, 16, 16, __half, wmma::row_major> fb;
            wmma::load_matrix_sync(fb, &Bs[k0][wn * 64 + j * 16], PBS_LD);
            wmma::mma_sync(fc[j], fa, fb, fc[j]);
        }
    }
    __syncthreads();   // done reading As/Bs; reuse as Cs
    #pragma unroll
    for (int j = 0; j < 4; ++j)
        wmma::store_matrix_sync(&Cs[wm * 16][wn * 64 + j * 16], fc[j], PCS_LD,
                                wmma::mem_row_major);
    __syncthreads();

    // fused e-vec for both heads (interleaved [n][4] layout) -- fp32, exact logits
    {
        const int row = tid >> 2, q = tid & 3;
        #pragma unroll
        for (int hh = 0; hh < 2; ++hh) {
            const int hg = z * 2 + hh;           // global head
            float s1 = 0.f, s2 = 0.f;
            #pragma unroll
            for (int i = 0; i < 16; ++i) {
                int cl = hh * 64 + q * 16 + i;
                float v = Cs[row][cl];
                s1 = fmaf(v, a1[hg * Ff + q * 16 + i], s1);
                s2 = fmaf(v, a2[hg * Ff + q * 16 + i], s2);
            }
            s1 += __shfl_xor_sync(0xffffffffu, s1, 1);
            s2 += __shfl_xor_sync(0xffffffffu, s2, 1);
            s1 += __shfl_xor_sync(0xffffffffu, s1, 2);
            s2 += __shfl_xor_sync(0xffffffffu, s2, 2);
            if (q == 0 && r0 + row < Nn) {
                g_e1v[(rowB + r0 + row) * 4 + hg] = s1;
                g_e2v[(rowB + r0 + row) * 4 + hg] = s2;
            }
        }
    }

    // fp16 Wh store (coalesced): 64 rows x 64 half2
    __half2* dst = (__half2*)g_Wh16;
    #pragma unroll
    for (int k = 0; k < 16; ++k) {
        int idx = k * 256 + tid;
        int r = idx >> 6, p = idx & 63;
        if (r0 + r < Nn) {
            dst[(rowB + r0 + r) * (HF / 2) + z * 64 + p] =
                __floats2half2_rn(Cs[r][2 * p], Cs[r][2 * p + 1]);
        }
    }
}

// ================= attention: SMEM-cached Wh tile, wide-LDS gather ==================
// grid (Hh, Ss), 512 threads (16 warps), 84KB dyn smem.
// Tile of 64 nodes: phase1 warp-per-node softmax -> sw[64][128] fp16;
// phase2: 4 nodes/warp, 8 lanes/node, LDS.128 per lane, HFMA2 accumulate. No shuffles.
#define ATTN_THREADS 512
#define TILE_N 64
#define SWH_BYTES (Nn * Ff * 2)                       // 64000
#define SE_BYTES (Nn * 4)                             // 2000 each
#define SW_OFF (SWH_BYTES + 2 * SE_BYTES)             // 68000
#define ATTN_SMEM (SW_OFF + TILE_N * MAXD * 2)        // 84384

__global__ __launch_bounds__(ATTN_THREADS)
void attn_agg() {
    extern __shared__ __align__(16) char asmem[];
    __half (*sWh)[Ff] = (__half(*)[Ff])asmem;
    float* sE1 = (float*)(asmem + SWH_BYTES);
    float* sE2 = (float*)(asmem + SWH_BYTES + SE_BYTES);
    __half (*sw)[MAXD] = (__half(*)[MAXD])(asmem + SW_OFF);

    const int h = blockIdx.x, s = blockIdx.y;
    const int tid = threadIdx.x;
    const int wid = tid >> 5, lane = tid & 31;
    const size_t rowB = (size_t)s * Nn;

    // stage: head slice of Wh (500 rows x 8 uint4) + e vectors
    {
        const uint4* src = (const uint4*)g_Wh16;     // row = 32 uint4
        for (int i = tid; i < Nn * 8; i += ATTN_THREADS) {
            int r = i >> 3, p = i & 7;
            *(uint4*)&sWh[r][p * 8] = src[(rowB + r) * 32 + h * 8 + p];
        }
        for (int i = tid; i < Nn; i += ATTN_THREADS) {
            sE1[i] = g_e1v[(rowB + i) * 4 + h];
            sE2[i] = g_e2v[(rowB + i) * 4 + h];
        }
    }
    __syncthreads();

    for (int tile = 0; tile < Nn; tile += TILE_N) {
        // ---- phase 1: softmax for 64 nodes (warp per node, 4 rounds) ----
        #pragma unroll
        for (int r = 0; r < TILE_N / 16; ++r) {
            const int nl = r * 16 + wid;
            const int n = tile + nl;
            if (n >= Nn) break;
            const int cnt = min(g_cnt[n], MAXD);
            const float e1v = sE1[n];
            float ev[4];
            float mx = -1e30f;
            #pragma unroll
            for (int k = 0; k < 4; ++k) {
                int j = k * 32 + lane;
                float e = -1e30f;
                if (k * 32 < cnt && j < cnt) {
                    int m = g_nbr[n * MAXD + j];
                    float tv = e1v + sE2[m];
                    e = tv > 0.f ? tv : LEAKc * tv;
                }
                ev[k] = e;
                mx = fmaxf(mx, e);
            }
            #pragma unroll
            for (int o = 16; o; o >>= 1)
                mx = fmaxf(mx, __shfl_xor_sync(0xffffffffu, mx, o));
            float sum = 0.f;
            #pragma unroll
            for (int k = 0; k < 4; ++k) {
                float w = (k * 32 + lane < cnt) ? __expf(ev[k] - mx) : 0.f;
                ev[k] = w;
                sum += w;
            }
            #pragma unroll
            for (int o = 16; o; o >>= 1) sum += __shfl_xor_sync(0xffffffffu, sum, o);
            const float inv = 1.f / sum;
            #pragma unroll
            for (int k = 0; k < 4; ++k) {
                int j = k * 32 + lane;
                if (j < cnt) sw[nl][j] = __float2half_rn(ev[k] * inv);
            }
        }
        __syncthreads();

        // ---- phase 2: gather. warp wid -> nodes tile + wid*4 + g, lane chunk c ----
        {
            const int g = lane >> 3, c = lane & 7;
            const int nl = wid * 4 + g;
            const int n = tile + nl;
            const bool act = (n < Nn);
            const int cnt = act ? min(g_cnt[n], MAXD) : 0;
            const int* nbrp = g_nbr + n * MAXD;
            __half2 a0 = __float2half2_rn(0.f), a1h = a0, a2h = a0, a3h = a0;
            for (int j = 0; j < cnt; ++j) {
                int m = nbrp[j];
                __half2 w2 = __half2half2(sw[nl][j]);
                uint4 v = *(const uint4*)&sWh[m][c * 8];
                a0 = __hfma2(*(__half2*)&v.x, w2, a0);
                a1h = __hfma2(*(__half2*)&v.y, w2, a1h);
                a2h = __hfma2(*(__half2*)&v.z, w2, a2h);
                a3h = __hfma2(*(__half2*)&v.w, w2, a3h);
            }
            if (act) {
                float2 f0 = __half22float2(a0);
                float2 f1 = __half22float2(a1h);
                float2 f2 = __half22float2(a2h);
                float2 f3 = __half22float2(a3h);
                float vv[8] = {f0.x, f0.y, f1.x, f1.y, f2.x, f2.y, f3.x, f3.y};
                #pragma unroll
                for (int i = 0; i < 8; ++i)
                    vv[i] = vv[i] > 0.f ? vv[i] : (__expf(vv[i]) - 1.f);
                __half2 o2[4];
                #pragma unroll
                for (int i = 0; i < 4; ++i)
                    o2[i] = __floats2half2_rn(vv[2 * i], vv[2 * i + 1]);
                // row = 32 uint4 (512B); head slot = 8 uint4; lane chunk c
                ((uint4*)g_hpr16)[(rowB + n) * 32 + h * 8 + c] = *(uint4*)o2;
            }
        }
        __syncthreads();
    }
}

// ================= fp16 wmma mix GEMM: h_next16 = a*x16 + (1-a)*(hpr16 @ WgT16 + bg) ==
// grid (Ss, 8), block 256 (8 warps). A fragments loaded straight from global.
#define MBS_LD 72
__global__ void gemm_mix_tc(const float* __restrict__ bias,
                            const __half* __restrict__ resid16,
                            __half* __restrict__ Cm16) {
    __shared__ __align__(16) char smemRaw[256 * MBS_LD * 2];   // Bs, reused as Cs
    __half (*Bs)[MBS_LD] = (__half(*)[MBS_LD])smemRaw;
    float (*Cs)[68] = (float(*)[68])smemRaw;                   // 17408 <= 36864

    const int s = blockIdx.x;
    const int r0 = blockIdx.y * 64;
    const int tid = threadIdx.x;
    const int wid = tid >> 5;
    const int wm = wid & 3, wn = wid >> 2;

    // stage B: 256 rows x 64 halfs (8 uint4/row), 8 uint4/thread
    {
        const uint4* src = (const uint4*)g_WgT16;
        #pragma unroll
        for (int k = 0; k < 8; ++k) {
            int idx = k * 256 + tid;
            int r = idx >> 3, p = idx & 7;
            *(uint4*)&Bs[r][p * 8] = src[r * 8 + p];
        }
    }
    __syncthreads();

    const __half* Aslice = g_hpr16 + (size_t)s * Nn * HF;      // padded tail -> safe OOB rows
    wmma::fragment<wmma::accumulator, 16, 16, 16, float> fc[2];
    wmma::fill_fragment(fc[0], 0.f);
    wmma::fill_fragment(fc[1], 0.f);
    #pragma unroll
    for (int k0 = 0; k0 < HF; k0 += 16) {
        wmma::fragment<wmma::matrix_a, 16, 16, 16, __half, wmma::row_major> fa;
        wmma::load_matrix_sync(fa, Aslice + (size_t)(r0 + wm * 16) * HF + k0, HF);
        #pragma unroll
        for (int sub = 0; sub < 2; ++sub) {
            wmma::fragment<wmma::matrix_b, 16, 16, 16, __half, wmma::row_major> fb;
            wmma::load_matrix_sync(fb, &Bs[k0][wn * 32 + sub * 16], MBS_LD);
            wmma::mma_sync(fc[sub], fa, fb, fc[sub]);
        }
    }
    __syncthreads();   // all warps done reading Bs; reuse as Cs
    wmma::store_matrix_sync(&Cs[wm * 16][wn * 32], fc[0], 68, wmma::mem_row_major);
    wmma::store_matrix_sync(&Cs[wm * 16][wn * 32 + 16], fc[1], 68, wmma::mem_row_major);
    __syncthreads();

    #pragma unroll
    for (int k = 0; k < 16; ++k) {
        int idx = k * 256 + tid;
        int r = idx >> 6, c = idx & 63;
        int row = r0 + r;
        if (row < Nn) {
            size_t oidx = ((size_t)s * Nn + row) * Cc + c;
            float v = ALPHAc * __half2float(resid16[oidx])
                    + (1.f - ALPHAc) * (Cs[r][c] + bias[c]);
            Cm16[oidx] = __float2half_rn(v);
        }
    }
}

// ---------------- final: out[b,o,n,t] = bm[o] + Wm @ [x; h1; h2] ----------------
__global__ void final_out(const float* __restrict__ xT,
                          const __half* __restrict__ h1,
                          const __half* __restrict__ h2,
                          const float* __restrict__ bm,
                          float* __restrict__ out) {
    __shared__ float sX[16][64], sH1[16][64], sH2[16][64];
    const int s = blockIdx.x;
    const int n0 = blockIdx.y * 16;
    const int tid = threadIdx.x;
    for (int i = tid; i < 16 * 64; i += 256) {
        int nl = i >> 6, c = i & 63;
        int n = n0 + nl;
        size_t idx = ((size_t)s * Nn + (n < Nn ? n : 0)) * Cc + c;
        sX[nl][c]  = (n < Nn) ? xT[idx] : 0.f;
        sH1[nl][c] = (n < Nn) ? __half2float(h1[idx]) : 0.f;
        sH2[nl][c] = (n < Nn) ? __half2float(h2[idx]) : 0.f;
    }
    __syncthreads();
    const int o = tid & 63, ng = tid >> 6;
    float acc[4] = {0.f, 0.f, 0.f, 0.f};
    #pragma unroll 4
    for (int c = 0; c < 64; ++c) {
        float w0 = g_WmT[c * Cc + o];
        float w1 = g_WmT[(64 + c) * Cc + o];
        float w2 = g_WmT[(128 + c) * Cc + o];
        #pragma unroll
        for (int r = 0; r < 4; ++r) {
            int nl = ng + r * 4;
            acc[r] = fmaf(w0, sX[nl][c], fmaf(w1, sH1[nl][c], fmaf(w2, sH2[nl][c], acc[r])));
        }
    }
    const int b = s / Tt, t = s % Tt;
    const float bias = bm[o];
    #pragma unroll
    for (int r = 0; r < 4; ++r) {
        int n = n0 + ng + r * 4;
        if (n < Nn)
            out[(((size_t)b * Cc + o) * Nn + n) * Tt + t] = acc[r] + bias;
    }
}

// ---------------- launch ----------------
extern "C" void kernel_launch(void* const* d_in, const int* in_sizes, int n_in,
                              void* d_out, int out_size) {
    const float* x   = (const float*)d_in[0];
    const float* adj = (const float*)d_in[1];
    const float* W   = (const float*)d_in[2];
    const float* a1  = (const float*)d_in[3];
    const float* a2  = (const float*)d_in[4];
    const float* Wg  = (const float*)d_in[5];
    const float* bg  = (const float*)d_in[6];
    const float* Wm  = (const float*)d_in[7];
    const float* bm  = (const float*)d_in[8];
    float* out = (float*)d_out;

    float* xT;
    __half *xT16, *h1T16, *h2T16;
    cudaGetSymbolAddress((void**)&xT,    g_xT);
    cudaGetSymbolAddress((void**)&xT16,  g_xT16);
    cudaGetSymbolAddress((void**)&h1T16, g_h1T16);
    cudaGetSymbolAddress((void**)&h2T16, g_h2T16);

    static bool attr_set = false;
    if (!attr_set) {
        cudaFuncSetAttribute(attn_agg,
                             cudaFuncAttributeMaxDynamicSharedMemorySize, ATTN_SMEM);
        attr_set = true;
    }

    prep_all<<<1213, 256>>>(adj, W, Wg, Wm, x, xT);

    const __half* hin16 = xT16;
    __half* hb16[2] = {h1T16, h2T16};
    for (int it = 0; it < 2; ++it) {
        gemm_proj16<<<dim3(Ss, 8, 2), 256>>>(hin16, a1, a2);
        attn_agg<<<dim3(Hh, Ss), ATTN_THREADS, ATTN_SMEM>>>();
        gemm_mix_tc<<<dim3(Ss, 8), 256>>>(bg, xT16, hb16[it]);
        hin16 = hb16[it];
    }
    final_out<<<dim3(Ss, (Nn + 15) / 16), 256>>>(xT, h1T16, h2T16, bm, out);
}

// round 15
// speedup vs baseline: 1.4606x; 1.4606x over previous
#include <cuda_runtime.h>
#include <cuda_fp16.h>
#include <mma.h>
#include <cstdint>

using namespace nvcuda;

// Problem constants
#define Bb 8
#define Cc 64
#define Nn 500
#define Tt 12
#define Hh 4
#define Ff 64
#define Ss (Bb * Tt)   // 96 slices (b,t)
#define HF (Hh * Ff)   // 256
#define MAXD 128
#define ROWPAD 16
#define ALPHAc 0.05f
#define OMAc 0.95f
#define LEAKc 0.2f

// ---------------- scratch (device globals; no allocation) ----------------
__device__ __half  g_xT16[Ss * Nn * Cc];                 // [s,n,c] fp16
__device__ __half  g_h1T16[Ss * Nn * Cc];
__device__ __half  g_Wh16[(size_t)Ss * Nn * HF];         // [s,n,hf] fp16
__device__ __half  g_hpr16[((size_t)Ss * Nn + ROWPAD) * HF]; // padded for OOB frag rows
__device__ float   g_e1v[Ss * Nn * 4];                   // [(s*N+n)*4 + h]
__device__ float   g_e2v[Ss * Nn * 4];
__device__ __half  g_Wcat16[Cc * HF];                    // [c, h*F+f] fp16
__device__ __half  g_WgT16[HF * Cc];                     // [hf, o] fp16
__device__ __half  g_Wfin16[3 * Cc * Cc];                // 3 x [c][o] fp16 (Wm blocks^T)
__device__ int     g_cnt[Nn];
__device__ int     g_nbr[Nn * MAXD];

// ================= merged prep: nbr list + weight layouts + input transpose =========
__global__ void prep_all(const float* __restrict__ adj,
                         const float* __restrict__ W,
                         const float* __restrict__ Wg,
                         const float* __restrict__ Wm,
                         const float* __restrict__ x) {
    __shared__ float sm[16][193];
    const int blk = blockIdx.x;
    if (blk < 125) {
        if (threadIdx.x >= 128) return;
        int warp = threadIdx.x >> 5;
        int lane = threadIdx.x & 31;
        int n = blk * 4 + warp;
        if (n >= Nn) return;
        int base = 0;
        for (int m0 = 0; m0 < 512; m0 += 32) {
            int m = m0 + lane;
            bool p = (m < Nn) && (adj[n * Nn + m] > 0.f || m == n);
            unsigned mask = __ballot_sync(0xffffffffu, p);
            if (p) {
                int r = __popc(mask & ((1u << lane) - 1));
                if (base + r < MAXD) g_nbr[n * MAXD + base + r] = m;
            }
            base += __popc(mask);
        }
        if (lane == 0) g_cnt[n] = base < MAXD ? base : MAXD;
    } else if (blk < 189) {
        int i = (blk - 125) * 256 + threadIdx.x;
        if (i < Hh * Cc * Ff) {  // Wcat16[c, h*F+f] = W[h,c,f]
            int f = i % Ff; int rest = i / Ff;
            int c = rest % Cc; int h = rest / Cc;
            g_Wcat16[c * HF + h * Ff + f] = __float2half_rn(W[(h * Cc + c) * Ff + f]);
        }
        if (i < HF * Cc) {       // WgT16[hf, o] = half(Wg[o, hf])
            int o = i % Cc; int hf = i / Cc;
            g_WgT16[hf * Cc + o] = __float2half_rn(Wg[o * HF + hf]);
        }
        if (i < 3 * Cc * Cc) {   // Wfin16[wsel][c][o] = half(Wm[o][wsel*64 + c])
            int o = i % Cc; int cg = i / Cc;
            int wsel = cg >> 6, c = cg & 63;
            g_Wfin16[(wsel * Cc + c) * Cc + o] =
                __float2half_rn(Wm[o * (3 * Cc) + wsel * 64 + c]);
        }
    } else {
        // transpose: x[b,c,n,t] -> xT16[s,n,c]
        if (threadIdx.x >= 192) return;
        const int bi = blk - 189;
        const int nb = bi & 31, cb = (bi >> 5) & 3, b = bi >> 7;
        const int c0 = cb * 16, n0 = nb * 16;
        const int tt_ = threadIdx.x;
        const int ni_l = tt_ / 12, tl = tt_ % 12;
        const int n_l = n0 + ni_l;
        #pragma unroll
        for (int ci = 0; ci < 16; ++ci) {
            float v = 0.f;
            if (n_l < Nn)
                v = x[(((size_t)b * Cc + c0 + ci) * Nn + n_l) * Tt + tl];
            sm[ci][tt_] = v;
        }
        __syncthreads();
        #pragma unroll
        for (int rep = 0; rep < 16; ++rep) {
            int idx = rep * 192 + tt_;
            int ci = idx & 15;
            int rest = idx >> 4;
            int ni = rest / 12, t = rest % 12;
            int n = n0 + ni;
            if (n < Nn)
                g_xT16[(((size_t)(b * Tt + t) * Nn) + n) * Cc + c0 + ci] =
                    __float2half_rn(sm[ci][rest]);
        }
    }
}

// ================= fp16 HMMA projection GEMM (2 heads/block) + e-vec + fp16 Wh ======
// grid (Ss, 8, 2), block 256 (8 warps). Tile 64 rows x 128 cols (heads 2z, 2z+1), K=64.
#define PAS_LD 72
#define PBS_LD 136
#define PCS_LD 132
__global__ void gemm_proj16(const __half* __restrict__ Ain,
                            const float* __restrict__ a1,
                            const float* __restrict__ a2) {
    __shared__ __align__(16) char smemRaw[64 * PCS_LD * 4];      // 33792 B
    __half (*As)[PAS_LD] = (__half(*)[PAS_LD])smemRaw;           // 9216 B
    __half (*Bs)[PBS_LD] = (__half(*)[PBS_LD])(smemRaw + 64 * PAS_LD * 2); // 17408 B
    float (*Cs)[PCS_LD] = (float(*)[PCS_LD])smemRaw;             // reuse after MMA

    const int s = blockIdx.x;
    const int r0 = blockIdx.y * 64;
    const int z = blockIdx.z;            // head pair
    const int c0 = z * 128;
    const int tid = threadIdx.x;
    const int wid = tid >> 5;
    const int wm = wid & 3, wn = wid >> 2;   // rows wm*16, cols wn*64
    const size_t rowB = (size_t)s * Nn;

    // stage A: 64 rows x 64 halfs (8 uint4/row), 2 uint4/thread
    {
        const uint4* srcA = (const uint4*)(Ain + rowB * Cc);
        #pragma unroll
        for (int k = 0; k < 2; ++k) {
            int idx = k * 256 + tid;
            int r = idx >> 3, p = idx & 7;
            int row = r0 + r;
            uint4 v = make_uint4(0, 0, 0, 0);
            if (row < Nn) v = srcA[(size_t)row * 8 + p];
            *(uint4*)&As[r][p * 8] = v;
        }
    }
    // stage B: Wcat16 rows 0..63, cols c0..c0+127 (16 uint4/row), 4 uint4/thread
    {
        const uint4* srcB = (const uint4*)(g_Wcat16 + c0);
        #pragma unroll
        for (int k = 0; k < 4; ++k) {
            int idx = k * 256 + tid;
            int r = idx >> 4, p = idx & 15;
            *(uint4*)&Bs[r][p * 8] = srcB[r * 32 + p];   // row stride 256 half = 32 uint4
        }
    }
    __syncthreads();

    wmma::fragment<wmma::accumulator, 16, 16, 16, float> fc[4];
    #pragma unroll
    for (int j = 0; j < 4; ++j) wmma::fill_fragment(fc[j], 0.f);
    #pragma unroll
    for (int k0 = 0; k0 < 64; k0 += 16) {
        wmma::fragment<wmma::matrix_a, 16, 16, 16, __half, wmma::row_major> fa;
        wmma::load_matrix_sync(fa, &As[wm * 16][k0], PAS_LD);
        #pragma unroll
        for (int j = 0; j < 4; ++j) {
            wmma::fragment<wmma::matrix_b, 16, 16, 16, __half, wmma::row_major> fb;
            wmma::load_matrix_sync(fb, &Bs[k0][wn * 64 + j * 16], PBS_LD);
            wmma::mma_sync(fc[j], fa, fb, fc[j]);
        }
    }
    __syncthreads();   // done reading As/Bs; reuse as Cs
    #pragma unroll
    for (int j = 0; j < 4; ++j)
        wmma::store_matrix_sync(&Cs[wm * 16][wn * 64 + j * 16], fc[j], PCS_LD,
                                wmma::mem_row_major);
    __syncthreads();

    // fused e-vec for both heads (interleaved [n][4] layout) -- fp32, exact logits
    {
        const int row = tid >> 2, q = tid & 3;
        #pragma unroll
        for (int hh = 0; hh < 2; ++hh) {
            const int hg = z * 2 + hh;           // global head
            float s1 = 0.f, s2 = 0.f;
            #pragma unroll
            for (int i = 0; i < 16; ++i) {
                int cl = hh * 64 + q * 16 + i;
                float v = Cs[row][cl];
                s1 = fmaf(v, a1[hg * Ff + q * 16 + i], s1);
                s2 = fmaf(v, a2[hg * Ff + q * 16 + i], s2);
            }
            s1 += __shfl_xor_sync(0xffffffffu, s1, 1);
            s2 += __shfl_xor_sync(0xffffffffu, s2, 1);
            s1 += __shfl_xor_sync(0xffffffffu, s1, 2);
            s2 += __shfl_xor_sync(0xffffffffu, s2, 2);
            if (q == 0 && r0 + row < Nn) {
                g_e1v[(rowB + r0 + row) * 4 + hg] = s1;
                g_e2v[(rowB + r0 + row) * 4 + hg] = s2;
            }
        }
    }

    // fp16 Wh store (coalesced): 64 rows x 64 half2
    __half2* dst = (__half2*)g_Wh16;
    #pragma unroll
    for (int k = 0; k < 16; ++k) {
        int idx = k * 256 + tid;
        int r = idx >> 6, p = idx & 63;
        if (r0 + r < Nn) {
            dst[(rowB + r0 + r) * (HF / 2) + z * 64 + p] =
                __floats2half2_rn(Cs[r][2 * p], Cs[r][2 * p + 1]);
        }
    }
}

// ---------------- attention (R10 verbatim): block (n,s), 128 thr; HFMA2 gather ------
__global__ void attn_agg() {
    const int n = blockIdx.x, s = blockIdx.y;
    const int t = threadIdx.x;
    const int h = t >> 5, lane = t & 31;
    __shared__ int snbr[MAXD];
    __shared__ __half swh[Hh][MAXD];
    __shared__ __half2 sred[4][32][4];     // [gatherWarp][chunk][pair]

    const int cnt = min(g_cnt[n], MAXD);
    for (int j = t; j < cnt; j += 128) snbr[j] = g_nbr[n * MAXD + j];
    __syncthreads();

    const size_t rowB = (size_t)s * Nn;
    const float e1v = g_e1v[(rowB + n) * 4 + h];
    float ev[4];
    float mx = -1e30f;
    #pragma unroll
    for (int k = 0; k < 4; ++k) {
        int j = k * 32 + lane;
        float e = -1e30f;
        if (j < cnt) {
            float tv = e1v + g_e2v[(rowB + snbr[j]) * 4 + h];
            e = tv > 0.f ? tv : LEAKc * tv;
        }
        ev[k] = e;
        mx = fmaxf(mx, e);
    }
    #pragma unroll
    for (int o = 16; o; o >>= 1) mx = fmaxf(mx, __shfl_xor_sync(0xffffffffu, mx, o));
    float sum = 0.f;
    #pragma unroll
    for (int k = 0; k < 4; ++k) {
        float w = (k * 32 + lane < cnt) ? __expf(ev[k] - mx) : 0.f;
        ev[k] = w;
        sum += w;
    }
    #pragma unroll
    for (int o = 16; o; o >>= 1) sum += __shfl_xor_sync(0xffffffffu, sum, o);
    const float inv = 1.f / sum;
    #pragma unroll
    for (int k = 0; k < 4; ++k) {
        int j = k * 32 + lane;
        if (j < cnt) swh[h][j] = __float2half_rn(ev[k] * inv);
    }
    __syncthreads();

    const int g = t >> 5, c = t & 31;
    const int hc = c >> 3;
    const uint4* Whv = (const uint4*)g_Wh16;
    __half2 a0 = __float2half2_rn(0.f), a1h = a0, a2h = a0, a3h = a0;
    #pragma unroll 2
    for (int j0 = 0; j0 < cnt; j0 += 4) {
        int j = j0 + g;
        if (j < cnt) {
            int m = snbr[j];
            __half2 w2 = __half2half2(swh[hc][j]);
            uint4 v = Whv[(rowB + m) * 32 + c];
            a0 = __hfma2(*(__half2*)&v.x, w2, a0);
            a1h = __hfma2(*(__half2*)&v.y, w2, a1h);
            a2h = __hfma2(*(__half2*)&v.z, w2, a2h);
            a3h = __hfma2(*(__half2*)&v.w, w2, a3h);
        }
    }
    sred[g][c][0] = a0;
    sred[g][c][1] = a1h;
    sred[g][c][2] = a2h;
    sred[g][c][3] = a3h;
    __syncthreads();

    const int rc = t >> 2, rp = t & 3;
    float2 v0 = __half22float2(sred[0][rc][rp]);
    float2 v1 = __half22float2(sred[1][rc][rp]);
    float2 v2 = __half22float2(sred[2][rc][rp]);
    float2 v3 = __half22float2(sred[3][rc][rp]);
    float vx = v0.x + v1.x + v2.x + v3.x;
    float vy = v0.y + v1.y + v2.y + v3.y;
    vx = vx > 0.f ? vx : (__expf(vx) - 1.f);
    vy = vy > 0.f ? vy : (__expf(vy) - 1.f);
    ((__half2*)g_hpr16)[(rowB + n) * (HF / 2) + t] = __floats2half2_rn(vx, vy);
}

// ================= fusedA: mix1 (hpr1@WgT + resid) -> h1 tile -> proj2 + e-vec ======
// grid (Ss, 8), block 256. smem: Bs1/Wcat-chunk (36864) | C (33792) | Ht (9216)
#define FA_OFF_C 36864
#define FA_OFF_H (36864 + 33792)
#define FA_SMEM (FA_OFF_H + 9216)      // 79872
__global__ __launch_bounds__(256)
void fusedA(const float* __restrict__ bias,
            const __half* __restrict__ x16,
            __half* __restrict__ h1out,
            const float* __restrict__ a1,
            const float* __restrict__ a2) {
    extern __shared__ __align__(16) char fsm[];
    __half (*Bs1)[72] = (__half(*)[72])fsm;                  // 256x72 WgT
    __half (*Bs2)[PBS_LD] = (__half(*)[PBS_LD])fsm;          // reuse: Wcat chunk
    float (*C1)[68] = (float(*)[68])(fsm + FA_OFF_C);
    float (*C2)[PCS_LD] = (float(*)[PCS_LD])(fsm + FA_OFF_C);
    __half (*Ht)[72] = (__half(*)[72])(fsm + FA_OFF_H);

    const int s = blockIdx.x;
    const int r0 = blockIdx.y * 64;
    const int tid = threadIdx.x;
    const int wid = tid >> 5;
    const int wm = wid & 3, wn = wid >> 2;
    const size_t rowB = (size_t)s * Nn;

    // stage Bs1 = WgT16 (256 rows x 8 uint4)
    {
        const uint4* src = (const uint4*)g_WgT16;
        #pragma unroll
        for (int k = 0; k < 8; ++k) {
            int idx = k * 256 + tid;
            int r = idx >> 3, p = idx & 7;
            *(uint4*)&Bs1[r][p * 8] = src[r * 8 + p];
        }
    }
    __syncthreads();

    // mix wmma: A from global hpr (padded), B from Bs1
    {
        const __half* Aslice = g_hpr16 + rowB * HF;
        wmma::fragment<wmma::accumulator, 16, 16, 16, float> fc[2];
        wmma::fill_fragment(fc[0], 0.f);
        wmma::fill_fragment(fc[1], 0.f);
        #pragma unroll
        for (int k0 = 0; k0 < HF; k0 += 16) {
            wmma::fragment<wmma::matrix_a, 16, 16, 16, __half, wmma::row_major> fa;
            wmma::load_matrix_sync(fa, Aslice + (size_t)(r0 + wm * 16) * HF + k0, HF);
            #pragma unroll
            for (int sub = 0; sub < 2; ++sub) {
                wmma::fragment<wmma::matrix_b, 16, 16, 16, __half, wmma::row_major> fb;
                wmma::load_matrix_sync(fb, &Bs1[k0][wn * 32 + sub * 16], 72);
                wmma::mma_sync(fc[sub], fa, fb, fc[sub]);
            }
        }
        __syncthreads();
        wmma::store_matrix_sync(&C1[wm * 16][wn * 32], fc[0], 68, wmma::mem_row_major);
        wmma::store_matrix_sync(&C1[wm * 16][wn * 32 + 16], fc[1], 68, wmma::mem_row_major);
    }
    __syncthreads();

    // epilogue: h1 = a*x + (1-a)*(C1 + bg); keep in Ht smem + write global h1out
    {
        const __half2* xs = (const __half2*)x16;
        __half2* dst = (__half2*)h1out;
        #pragma unroll
        for (int k = 0; k < 8; ++k) {
            int idx = k * 256 + tid;              // 2048 = 64 rows x 32 half2
            int r = idx >> 5, pc = idx & 31;
            int row = r0 + r;
            float v0 = 0.f, v1 = 0.f;
            if (row < Nn) {
                float2 xv = __half22float2(xs[(rowB + row) * 32 + pc]);
                v0 = ALPHAc * xv.x + OMAc * (C1[r][2 * pc]     + bias[2 * pc]);
                v1 = ALPHAc * xv.y + OMAc * (C1[r][2 * pc + 1] + bias[2 * pc + 1]);
            }
            __half2 hv = __floats2half2_rn(v0, v1);
            *(__half2*)&Ht[r][2 * pc] = hv;
            if (row < Nn) dst[(rowB + row) * 32 + pc] = hv;
        }
    }
    __syncthreads();

    // proj2: two head-pair chunks
    for (int z = 0; z < 2; ++z) {
        const int c0 = z * 128;
        {
            const uint4* srcW = (const uint4*)(g_Wcat16 + c0);
            #pragma unroll
            for (int k = 0; k < 4; ++k) {
                int idx = k * 256 + tid;
                int r = idx >> 4, p = idx & 15;
                *(uint4*)&Bs2[r][p * 8] = srcW[r * 32 + p];
            }
        }
        __syncthreads();
        wmma::fragment<wmma::accumulator, 16, 16, 16, float> fc[4];
        #pragma unroll
        for (int j = 0; j < 4; ++j) wmma::fill_fragment(fc[j], 0.f);
        #pragma unroll
        for (int k0 = 0; k0 < 64; k0 += 16) {
            wmma::fragment<wmma::matrix_a, 16, 16, 16, __half, wmma::row_major> fa;
            wmma::load_matrix_sync(fa, &Ht[wm * 16][k0], 72);
            #pragma unroll
            for (int j = 0; j < 4; ++j) {
                wmma::fragment<wmma::matrix_b, 16, 16, 16, __half, wmma::row_major> fb;
                wmma::load_matrix_sync(fb, &Bs2[k0][wn * 64 + j * 16], PBS_LD);
                wmma::mma_sync(fc[j], fa, fb, fc[j]);
            }
        }
        __syncthreads();
        #pragma unroll
        for (int j = 0; j < 4; ++j)
            wmma::store_matrix_sync(&C2[wm * 16][wn * 64 + j * 16], fc[j], PCS_LD,
                                    wmma::mem_row_major);
        __syncthreads();

        // e-vec for heads 2z, 2z+1
        {
            const int row = tid >> 2, q = tid & 3;
            #pragma unroll
            for (int hh = 0; hh < 2; ++hh) {
                const int hg = z * 2 + hh;
                float s1 = 0.f, s2 = 0.f;
                #pragma unroll
                for (int i = 0; i < 16; ++i) {
                    float v = C2[row][hh * 64 + q * 16 + i];
                    s1 = fmaf(v, a1[hg * Ff + q * 16 + i], s1);
                    s2 = fmaf(v, a2[hg * Ff + q * 16 + i], s2);
                }
                s1 += __shfl_xor_sync(0xffffffffu, s1, 1);
                s2 += __shfl_xor_sync(0xffffffffu, s2, 1);
                s1 += __shfl_xor_sync(0xffffffffu, s1, 2);
                s2 += __shfl_xor_sync(0xffffffffu, s2, 2);
                if (q == 0 && r0 + row < Nn) {
                    g_e1v[(rowB + r0 + row) * 4 + hg] = s1;
                    g_e2v[(rowB + r0 + row) * 4 + hg] = s2;
                }
            }
        }
        // Wh2 store
        __half2* dst = (__half2*)g_Wh16;
        #pragma unroll
        for (int k = 0; k < 16; ++k) {
            int idx = k * 256 + tid;
            int r = idx >> 6, p = idx & 63;
            if (r0 + r < Nn) {
                dst[(rowB + r0 + r) * (HF / 2) + z * 64 + p] =
                    __floats2half2_rn(C2[r][2 * p], C2[r][2 * p + 1]);
            }
        }
        __syncthreads();
    }
}

// ================= fusedB: mix2 -> h2 tile (smem only) -> final HMMA -> out =========
// grid (Ss, 8), block 256. smem: Bs1/finB (36864) | C (17408) | tiles x,h1,h2 (27648)
#define FB_OFF_C 36864
#define FB_OFF_T (36864 + 17408)
#define FB_SMEM (FB_OFF_T + 27648)     // 81920
__global__ __launch_bounds__(256)
void fusedB(const float* __restrict__ bias,
            const float* __restrict__ bm,
            const __half* __restrict__ x16,
            const __half* __restrict__ h1in,
            float* __restrict__ out) {
    extern __shared__ __align__(16) char fsm[];
    __half (*Bs1)[72] = (__half(*)[72])fsm;                  // 256x72 WgT
    __half (*FB)[72] = (__half(*)[72])fsm;                   // reuse: 192x72 final B
    float (*C1)[68] = (float(*)[68])(fsm + FB_OFF_C);
    __half (*Tl)[72] = (__half(*)[72])(fsm + FB_OFF_T);      // 192 rows: x | h1 | h2

    const int s = blockIdx.x;
    const int r0 = blockIdx.y * 64;
    const int tid = threadIdx.x;
    const int wid = tid >> 5;
    const int wm = wid & 3, wn = wid >> 2;
    const size_t rowB = (size_t)s * Nn;

    // stage Bs1 = WgT16 + x/h1 tiles
    {
        const uint4* src = (const uint4*)g_WgT16;
        #pragma unroll
        for (int k = 0; k < 8; ++k) {
            int idx = k * 256 + tid;
            int r = idx >> 3, p = idx & 7;
            *(uint4*)&Bs1[r][p * 8] = src[r * 8 + p];
        }
        const uint4* sx = (const uint4*)x16;
        const uint4* sh = (const uint4*)h1in;
        #pragma unroll
        for (int k = 0; k < 2; ++k) {
            int idx = k * 256 + tid;              // 512 = 64 rows x 8 uint4
            int r = idx >> 3, p = idx & 7;
            int row = r0 + r;
            uint4 vx = make_uint4(0, 0, 0, 0), vh = vx;
            if (row < Nn) {
                vx = sx[(rowB + row) * 8 + p];
                vh = sh[(rowB + row) * 8 + p];
            }
            *(uint4*)&Tl[r][p * 8] = vx;
            *(uint4*)&Tl[64 + r][p * 8] = vh;
        }
    }
    __syncthreads();

    // mix wmma (A global hpr2, B = Bs1)
    {
        const __half* Aslice = g_hpr16 + rowB * HF;
        wmma::fragment<wmma::accumulator, 16, 16, 16, float> fc[2];
        wmma::fill_fragment(fc[0], 0.f);
        wmma::fill_fragment(fc[1], 0.f);
        #pragma unroll
        for (int k0 = 0; k0 < HF; k0 += 16) {
            wmma::fragment<wmma::matrix_a, 16, 16, 16, __half, wmma::row_major> fa;
            wmma::load_matrix_sync(fa, Aslice + (size_t)(r0 + wm * 16) * HF + k0, HF);
            #pragma unroll
            for (int sub = 0; sub < 2; ++sub) {
                wmma::fragment<wmma::matrix_b, 16, 16, 16, __half, wmma::row_major> fb;
                wmma::load_matrix_sync(fb, &Bs1[k0][wn * 32 + sub * 16], 72);
                wmma::mma_sync(fc[sub], fa, fb, fc[sub]);
            }
        }
        __syncthreads();
        wmma::store_matrix_sync(&C1[wm * 16][wn * 32], fc[0], 68, wmma::mem_row_major);
        wmma::store_matrix_sync(&C1[wm * 16][wn * 32 + 16], fc[1], 68, wmma::mem_row_major);
    }
    __syncthreads();

    // epilogue: h2 tile (smem only) ; stage final B (overwrites Bs1)
    {
        #pragma unroll
        for (int k = 0; k < 8; ++k) {
            int idx = k * 256 + tid;
            int r = idx >> 5, pc = idx & 31;
            int row = r0 + r;
            float v0 = 0.f, v1 = 0.f;
            if (row < Nn) {
                float2 xv = __half22float2(*(const __half2*)&Tl[r][2 * pc]);
                v0 = ALPHAc * xv.x + OMAc * (C1[r][2 * pc]     + bias[2 * pc]);
                v1 = ALPHAc * xv.y + OMAc * (C1[r][2 * pc + 1] + bias[2 * pc + 1]);
            }
            *(__half2*)&Tl[128 + r][2 * pc] = __floats2half2_rn(v0, v1);
        }
        const uint4* src = (const uint4*)g_Wfin16;   // 192 rows x 8 uint4
        #pragma unroll
        for (int k = 0; k < 6; ++k) {
            int idx = k * 256 + tid;
            int r = idx >> 3, p = idx & 7;
            *(uint4*)&FB[r][p * 8] = src[r * 8 + p];
        }
    }
    __syncthreads();

    // final wmma: out = x@Wx + h1@W1 + h2@W2, K = 3x64
    {
        wmma::fragment<wmma::accumulator, 16, 16, 16, float> fc[2];
        wmma::fill_fragment(fc[0], 0.f);
        wmma::fill_fragment(fc[1], 0.f);
        #pragma unroll
        for (int t3 = 0; t3 < 3; ++t3) {
            #pragma unroll
            for (int k0 = 0; k0 < 64; k0 += 16) {
                wmma::fragment<wmma::matrix_a, 16, 16, 16, __half, wmma::row_major> fa;
                wmma::load_matrix_sync(fa, &Tl[t3 * 64 + wm * 16][k0], 72);
                #pragma unroll
                for (int sub = 0; sub < 2; ++sub) {
                    wmma::fragment<wmma::matrix_b, 16, 16, 16, __half, wmma::row_major> fb;
                    wmma::load_matrix_sync(fb, &FB[t3 * 64 + k0][wn * 32 + sub * 16], 72);
                    wmma::mma_sync(fc[sub], fa, fb, fc[sub]);
                }
            }
        }
        __syncthreads();
        wmma::store_matrix_sync(&C1[wm * 16][wn * 32], fc[0], 68, wmma::mem_row_major);
        wmma::store_matrix_sync(&C1[wm * 16][wn * 32 + 16], fc[1], 68, wmma::mem_row_major);
    }
    __syncthreads();

    // out epilogue: out[b,c,n,t]
    const int b = s / Tt, t = s % Tt;
    #pragma unroll
    for (int k = 0; k < 16; ++k) {
        int idx = k * 256 + tid;
        int r = idx >> 6, c = idx & 63;
        int row = r0 + r;
        if (row < Nn)
            out[(((size_t)b * Cc + c) * Nn + row) * Tt + t] = C1[r][c] + bm[c];
    }
}

// ---------------- launch ----------------
extern "C" void kernel_launch(void* const* d_in, const int* in_sizes, int n_in,
                              void* d_out, int out_size) {
    const float* x   = (const float*)d_in[0];
    const float* adj = (const float*)d_in[1];
    const float* W   = (const float*)d_in[2];
    const float* a1  = (const float*)d_in[3];
    const float* a2  = (const float*)d_in[4];
    const float* Wg  = (const float*)d_in[5];
    const float* bg  = (const float*)d_in[6];
    const float* Wm  = (const float*)d_in[7];
    const float* bm  = (const float*)d_in[8];
    float* out = (float*)d_out;

    __half *xT16, *h1T16;
    cudaGetSymbolAddress((void**)&xT16,  g_xT16);
    cudaGetSymbolAddress((void**)&h1T16, g_h1T16);

    static bool attr_set = false;
    if (!attr_set) {
        cudaFuncSetAttribute(fusedA, cudaFuncAttributeMaxDynamicSharedMemorySize, FA_SMEM);
        cudaFuncSetAttribute(fusedB, cudaFuncAttributeMaxDynamicSharedMemorySize, FB_SMEM);
        attr_set = true;
    }

    prep_all<<<1213, 256>>>(adj, W, Wg, Wm, x);
    gemm_proj16<<<dim3(Ss, 8, 2), 256>>>(xT16, a1, a2);
    attn_agg<<<dim3(Nn, Ss), 128>>>();
    fusedA<<<dim3(Ss, 8), 256, FA_SMEM>>>(bg, xT16, h1T16, a1, a2);
    attn_agg<<<dim3(Nn, Ss), 128>>>();
    fusedB<<<dim3(Ss, 8), 256, FB_SMEM>>>(bg, bm, xT16, h1T16, out);
}

// round 16
// speedup vs baseline: 1.5323x; 1.0491x over previous
#include <cuda_runtime.h>
#include <cuda_fp16.h>
#include <mma.h>
#include <cstdint>

using namespace nvcuda;

// Problem constants
#define Bb 8
#define Cc 64
#define Nn 500
#define Tt 12
#define Hh 4
#define Ff 64
#define Ss (Bb * Tt)   // 96 slices (b,t)
#define HF (Hh * Ff)   // 256
#define MAXD 128
#define ROWPAD 16
#define ALPHAc 0.05f
#define OMAc 0.95f
#define LEAKc 0.2f

// ---------------- scratch (device globals; no allocation) ----------------
__device__ __half  g_xT16[Ss * Nn * Cc];                 // [s,n,c] fp16
__device__ __half  g_h1T16[Ss * Nn * Cc];
__device__ __half  g_Wh16[(size_t)Ss * Nn * HF];         // [s,n,hf] fp16
__device__ __half  g_hpr16[((size_t)Ss * Nn + ROWPAD) * HF]; // padded for OOB frag rows
__device__ float   g_e1v[Ss * Nn * 4];                   // [(s*N+n)*4 + h]
__device__ float   g_e2v[Ss * Nn * 4];
__device__ __half  g_Wcat16[Cc * HF];                    // [c, h*F+f] fp16
__device__ __half  g_WgT16[HF * Cc];                     // [hf, o] fp16
__device__ __half  g_Wfin16[3 * Cc * Cc];                // 3 x [c][o] fp16 (Wm blocks^T)
__device__ int     g_cnt[Nn];
__device__ int     g_nbr[Nn * MAXD];

// ================= merged prep: nbr list + weight layouts + input transpose =========
__global__ void prep_all(const float* __restrict__ adj,
                         const float* __restrict__ W,
                         const float* __restrict__ Wg,
                         const float* __restrict__ Wm,
                         const float* __restrict__ x) {
    __shared__ float sm[16][193];
    const int blk = blockIdx.x;
    if (blk < 125) {
        if (threadIdx.x >= 128) return;
        int warp = threadIdx.x >> 5;
        int lane = threadIdx.x & 31;
        int n = blk * 4 + warp;
        if (n >= Nn) return;
        int base = 0;
        for (int m0 = 0; m0 < 512; m0 += 32) {
            int m = m0 + lane;
            bool p = (m < Nn) && (adj[n * Nn + m] > 0.f || m == n);
            unsigned mask = __ballot_sync(0xffffffffu, p);
            if (p) {
                int r = __popc(mask & ((1u << lane) - 1));
                if (base + r < MAXD) g_nbr[n * MAXD + base + r] = m;
            }
            base += __popc(mask);
        }
        if (lane == 0) g_cnt[n] = base < MAXD ? base : MAXD;
    } else if (blk < 189) {
        int i = (blk - 125) * 256 + threadIdx.x;
        if (i < Hh * Cc * Ff) {  // Wcat16[c, h*F+f] = W[h,c,f]
            int f = i % Ff; int rest = i / Ff;
            int c = rest % Cc; int h = rest / Cc;
            g_Wcat16[c * HF + h * Ff + f] = __float2half_rn(W[(h * Cc + c) * Ff + f]);
        }
        if (i < HF * Cc) {       // WgT16[hf, o] = half(Wg[o, hf])
            int o = i % Cc; int hf = i / Cc;
            g_WgT16[hf * Cc + o] = __float2half_rn(Wg[o * HF + hf]);
        }
        if (i < 3 * Cc * Cc) {   // Wfin16[wsel][c][o] = half(Wm[o][wsel*64 + c])
            int o = i % Cc; int cg = i / Cc;
            int wsel = cg >> 6, c = cg & 63;
            g_Wfin16[(wsel * Cc + c) * Cc + o] =
                __float2half_rn(Wm[o * (3 * Cc) + wsel * 64 + c]);
        }
    } else {
        // transpose: x[b,c,n,t] -> xT16[s,n,c]
        if (threadIdx.x >= 192) return;
        const int bi = blk - 189;
        const int nb = bi & 31, cb = (bi >> 5) & 3, b = bi >> 7;
        const int c0 = cb * 16, n0 = nb * 16;
        const int tt_ = threadIdx.x;
        const int ni_l = tt_ / 12, tl = tt_ % 12;
        const int n_l = n0 + ni_l;
        #pragma unroll
        for (int ci = 0; ci < 16; ++ci) {
            float v = 0.f;
            if (n_l < Nn)
                v = x[(((size_t)b * Cc + c0 + ci) * Nn + n_l) * Tt + tl];
            sm[ci][tt_] = v;
        }
        __syncthreads();
        #pragma unroll
        for (int rep = 0; rep < 16; ++rep) {
            int idx = rep * 192 + tt_;
            int ci = idx & 15;
            int rest = idx >> 4;
            int ni = rest / 12, t = rest % 12;
            int n = n0 + ni;
            if (n < Nn)
                g_xT16[(((size_t)(b * Tt + t) * Nn) + n) * Cc + c0 + ci] =
                    __float2half_rn(sm[ci][rest]);
        }
    }
}

// ================= fp16 HMMA projection GEMM (2 heads/block) + e-vec + fp16 Wh ======
// grid (Ss, 8, 2), block 256 (8 warps). Tile 64 rows x 128 cols (heads 2z, 2z+1), K=64.
#define PAS_LD 72
#define PBS_LD 136
#define PCS_LD 132
__global__ void gemm_proj16(const __half* __restrict__ Ain,
                            const float* __restrict__ a1,
                            const float* __restrict__ a2) {
    __shared__ __align__(16) char smemRaw[64 * PCS_LD * 4];      // 33792 B
    __half (*As)[PAS_LD] = (__half(*)[PAS_LD])smemRaw;           // 9216 B
    __half (*Bs)[PBS_LD] = (__half(*)[PBS_LD])(smemRaw + 64 * PAS_LD * 2); // 17408 B
    float (*Cs)[PCS_LD] = (float(*)[PCS_LD])smemRaw;             // reuse after MMA

    const int s = blockIdx.x;
    const int r0 = blockIdx.y * 64;
    const int z = blockIdx.z;            // head pair
    const int c0 = z * 128;
    const int tid = threadIdx.x;
    const int wid = tid >> 5;
    const int wm = wid & 3, wn = wid >> 2;   // rows wm*16, cols wn*64
    const size_t rowB = (size_t)s * Nn;

    // stage A: 64 rows x 64 halfs (8 uint4/row), 2 uint4/thread
    {
        const uint4* srcA = (const uint4*)(Ain + rowB * Cc);
        #pragma unroll
        for (int k = 0; k < 2; ++k) {
            int idx = k * 256 + tid;
            int r = idx >> 3, p = idx & 7;
            int row = r0 + r;
            uint4 v = make_uint4(0, 0, 0, 0);
            if (row < Nn) v = srcA[(size_t)row * 8 + p];
            *(uint4*)&As[r][p * 8] = v;
        }
    }
    // stage B: Wcat16 rows 0..63, cols c0..c0+127 (16 uint4/row), 4 uint4/thread
    {
        const uint4* srcB = (const uint4*)(g_Wcat16 + c0);
        #pragma unroll
        for (int k = 0; k < 4; ++k) {
            int idx = k * 256 + tid;
            int r = idx >> 4, p = idx & 15;
            *(uint4*)&Bs[r][p * 8] = srcB[r * 32 + p];   // row stride 256 half = 32 uint4
        }
    }
    __syncthreads();

    wmma::fragment<wmma::accumulator, 16, 16, 16, float> fc[4];
    #pragma unroll
    for (int j = 0; j < 4; ++j) wmma::fill_fragment(fc[j], 0.f);
    #pragma unroll
    for (int k0 = 0; k0 < 64; k0 += 16) {
        wmma::fragment<wmma::matrix_a, 16, 16, 16, __half, wmma::row_major> fa;
        wmma::load_matrix_sync(fa, &As[wm * 16][k0], PAS_LD);
        #pragma unroll
        for (int j = 0; j < 4; ++j) {
            wmma::fragment<wmma::matrix_b, 16, 16, 16, __half, wmma::row_major> fb;
            wmma::load_matrix_sync(fb, &Bs[k0][wn * 64 + j * 16], PBS_LD);
            wmma::mma_sync(fc[j], fa, fb, fc[j]);
        }
    }
    __syncthreads();   // done reading As/Bs; reuse as Cs
    #pragma unroll
    for (int j = 0; j < 4; ++j)
        wmma::store_matrix_sync(&Cs[wm * 16][wn * 64 + j * 16], fc[j], PCS_LD,
                                wmma::mem_row_major);
    __syncthreads();

    // fused e-vec for both heads (interleaved [n][4] layout) -- fp32, exact logits
    {
        const int row = tid >> 2, q = tid & 3;
        #pragma unroll
        for (int hh = 0; hh < 2; ++hh) {
            const int hg = z * 2 + hh;           // global head
            float s1 = 0.f, s2 = 0.f;
            #pragma unroll
            for (int i = 0; i < 16; ++i) {
                int cl = hh * 64 + q * 16 + i;
                float v = Cs[row][cl];
                s1 = fmaf(v, a1[hg * Ff + q * 16 + i], s1);
                s2 = fmaf(v, a2[hg * Ff + q * 16 + i], s2);
            }
            s1 += __shfl_xor_sync(0xffffffffu, s1, 1);
            s2 += __shfl_xor_sync(0xffffffffu, s2, 1);
            s1 += __shfl_xor_sync(0xffffffffu, s1, 2);
            s2 += __shfl_xor_sync(0xffffffffu, s2, 2);
            if (q == 0 && r0 + row < Nn) {
                g_e1v[(rowB + r0 + row) * 4 + hg] = s1;
                g_e2v[(rowB + r0 + row) * 4 + hg] = s2;
            }
        }
    }

    // fp16 Wh store (coalesced): 64 rows x 64 half2
    __half2* dst = (__half2*)g_Wh16;
    #pragma unroll
    for (int k = 0; k < 16; ++k) {
        int idx = k * 256 + tid;
        int r = idx >> 6, p = idx & 63;
        if (r0 + r < Nn) {
            dst[(rowB + r0 + r) * (HF / 2) + z * 64 + p] =
                __floats2half2_rn(Cs[r][2 * p], Cs[r][2 * p + 1]);
        }
    }
}

// ---------------- attention (R10 verbatim): block (n,s), 128 thr; HFMA2 gather ------
__global__ void attn_agg() {
    const int n = blockIdx.x, s = blockIdx.y;
    const int t = threadIdx.x;
    const int h = t >> 5, lane = t & 31;
    __shared__ int snbr[MAXD];
    __shared__ __half swh[Hh][MAXD];
    __shared__ __half2 sred[4][32][4];     // [gatherWarp][chunk][pair]

    const int cnt = min(g_cnt[n], MAXD);
    for (int j = t; j < cnt; j += 128) snbr[j] = g_nbr[n * MAXD + j];
    __syncthreads();

    const size_t rowB = (size_t)s * Nn;
    const float e1v = g_e1v[(rowB + n) * 4 + h];
    float ev[4];
    float mx = -1e30f;
    #pragma unroll
    for (int k = 0; k < 4; ++k) {
        int j = k * 32 + lane;
        float e = -1e30f;
        if (j < cnt) {
            float tv = e1v + g_e2v[(rowB + snbr[j]) * 4 + h];
            e = tv > 0.f ? tv : LEAKc * tv;
        }
        ev[k] = e;
        mx = fmaxf(mx, e);
    }
    #pragma unroll
    for (int o = 16; o; o >>= 1) mx = fmaxf(mx, __shfl_xor_sync(0xffffffffu, mx, o));
    float sum = 0.f;
    #pragma unroll
    for (int k = 0; k < 4; ++k) {
        float w = (k * 32 + lane < cnt) ? __expf(ev[k] - mx) : 0.f;
        ev[k] = w;
        sum += w;
    }
    #pragma unroll
    for (int o = 16; o; o >>= 1) sum += __shfl_xor_sync(0xffffffffu, sum, o);
    const float inv = 1.f / sum;
    #pragma unroll
    for (int k = 0; k < 4; ++k) {
        int j = k * 32 + lane;
        if (j < cnt) swh[h][j] = __float2half_rn(ev[k] * inv);
    }
    __syncthreads();

    const int g = t >> 5, c = t & 31;
    const int hc = c >> 3;
    const uint4* Whv = (const uint4*)g_Wh16;
    __half2 a0 = __float2half2_rn(0.f), a1h = a0, a2h = a0, a3h = a0;
    #pragma unroll 2
    for (int j0 = 0; j0 < cnt; j0 += 4) {
        int j = j0 + g;
        if (j < cnt) {
            int m = snbr[j];
            __half2 w2 = __half2half2(swh[hc][j]);
            uint4 v = Whv[(rowB + m) * 32 + c];
            a0 = __hfma2(*(__half2*)&v.x, w2, a0);
            a1h = __hfma2(*(__half2*)&v.y, w2, a1h);
            a2h = __hfma2(*(__half2*)&v.z, w2, a2h);
            a3h = __hfma2(*(__half2*)&v.w, w2, a3h);
        }
    }
    sred[g][c][0] = a0;
    sred[g][c][1] = a1h;
    sred[g][c][2] = a2h;
    sred[g][c][3] = a3h;
    __syncthreads();

    const int rc = t >> 2, rp = t & 3;
    float2 v0 = __half22float2(sred[0][rc][rp]);
    float2 v1 = __half22float2(sred[1][rc][rp]);
    float2 v2 = __half22float2(sred[2][rc][rp]);
    float2 v3 = __half22float2(sred[3][rc][rp]);
    float vx = v0.x + v1.x + v2.x + v3.x;
    float vy = v0.y + v1.y + v2.y + v3.y;
    vx = vx > 0.f ? vx : (__expf(vx) - 1.f);
    vy = vy > 0.f ? vy : (__expf(vy) - 1.f);
    ((__half2*)g_hpr16)[(rowB + n) * (HF / 2) + t] = __floats2half2_rn(vx, vy);
}

// ================= fusedA: mix1 (hpr1@WgT + resid) -> h1 tile -> proj2 + e-vec ======
// grid (Ss, 8), block 256, 2 blocks/SM forced (reg cap 128).
#define FA_OFF_C 36864
#define FA_OFF_H (36864 + 33792)
#define FA_SMEM (FA_OFF_H + 9216)      // 79872
__global__ __launch_bounds__(256, 2)
void fusedA(const float* __restrict__ bias,
            const __half* __restrict__ x16,
            __half* __restrict__ h1out,
            const float* __restrict__ a1,
            const float* __restrict__ a2) {
    extern __shared__ __align__(16) char fsm[];
    __half (*Bs1)[72] = (__half(*)[72])fsm;                  // 256x72 WgT
    __half (*Bs2)[PBS_LD] = (__half(*)[PBS_LD])fsm;          // reuse: Wcat chunk
    float (*C1)[68] = (float(*)[68])(fsm + FA_OFF_C);
    float (*C2)[PCS_LD] = (float(*)[PCS_LD])(fsm + FA_OFF_C);
    __half (*Ht)[72] = (__half(*)[72])(fsm + FA_OFF_H);

    const int s = blockIdx.x;
    const int r0 = blockIdx.y * 64;
    const int tid = threadIdx.x;
    const int wid = tid >> 5;
    const int wm = wid & 3, wn = wid >> 2;
    const size_t rowB = (size_t)s * Nn;

    // stage Bs1 = WgT16 (256 rows x 8 uint4)
    {
        const uint4* src = (const uint4*)g_WgT16;
        #pragma unroll
        for (int k = 0; k < 8; ++k) {
            int idx = k * 256 + tid;
            int r = idx >> 3, p = idx & 7;
            *(uint4*)&Bs1[r][p * 8] = src[r * 8 + p];
        }
    }
    __syncthreads();

    // mix wmma: A from global hpr (padded), B from Bs1
    {
        const __half* Aslice = g_hpr16 + rowB * HF;
        wmma::fragment<wmma::accumulator, 16, 16, 16, float> fc[2];
        wmma::fill_fragment(fc[0], 0.f);
        wmma::fill_fragment(fc[1], 0.f);
        #pragma unroll
        for (int k0 = 0; k0 < HF; k0 += 16) {
            wmma::fragment<wmma::matrix_a, 16, 16, 16, __half, wmma::row_major> fa;
            wmma::load_matrix_sync(fa, Aslice + (size_t)(r0 + wm * 16) * HF + k0, HF);
            #pragma unroll
            for (int sub = 0; sub < 2; ++sub) {
                wmma::fragment<wmma::matrix_b, 16, 16, 16, __half, wmma::row_major> fb;
                wmma::load_matrix_sync(fb, &Bs1[k0][wn * 32 + sub * 16], 72);
                wmma::mma_sync(fc[sub], fa, fb, fc[sub]);
            }
        }
        __syncthreads();
        wmma::store_matrix_sync(&C1[wm * 16][wn * 32], fc[0], 68, wmma::mem_row_major);
        wmma::store_matrix_sync(&C1[wm * 16][wn * 32 + 16], fc[1], 68, wmma::mem_row_major);
    }
    __syncthreads();

    // epilogue: h1 = a*x + (1-a)*(C1 + bg); keep in Ht smem + write global h1out
    {
        const __half2* xs = (const __half2*)x16;
        __half2* dst = (__half2*)h1out;
        #pragma unroll
        for (int k = 0; k < 8; ++k) {
            int idx = k * 256 + tid;              // 2048 = 64 rows x 32 half2
            int r = idx >> 5, pc = idx & 31;
            int row = r0 + r;
            float v0 = 0.f, v1 = 0.f;
            if (row < Nn) {
                float2 xv = __half22float2(xs[(rowB + row) * 32 + pc]);
                v0 = ALPHAc * xv.x + OMAc * (C1[r][2 * pc]     + bias[2 * pc]);
                v1 = ALPHAc * xv.y + OMAc * (C1[r][2 * pc + 1] + bias[2 * pc + 1]);
            }
            __half2 hv = __floats2half2_rn(v0, v1);
            *(__half2*)&Ht[r][2 * pc] = hv;
            if (row < Nn) dst[(rowB + row) * 32 + pc] = hv;
        }
    }
    __syncthreads();

    // proj2: two head-pair chunks
    for (int z = 0; z < 2; ++z) {
        const int c0 = z * 128;
        {
            const uint4* srcW = (const uint4*)(g_Wcat16 + c0);
            #pragma unroll
            for (int k = 0; k < 4; ++k) {
                int idx = k * 256 + tid;
                int r = idx >> 4, p = idx & 15;
                *(uint4*)&Bs2[r][p * 8] = srcW[r * 32 + p];
            }
        }
        __syncthreads();
        wmma::fragment<wmma::accumulator, 16, 16, 16, float> fc[4];
        #pragma unroll
        for (int j = 0; j < 4; ++j) wmma::fill_fragment(fc[j], 0.f);
        #pragma unroll
        for (int k0 = 0; k0 < 64; k0 += 16) {
            wmma::fragment<wmma::matrix_a, 16, 16, 16, __half, wmma::row_major> fa;
            wmma::load_matrix_sync(fa, &Ht[wm * 16][k0], 72);
            #pragma unroll
            for (int j = 0; j < 4; ++j) {
                wmma::fragment<wmma::matrix_b, 16, 16, 16, __half, wmma::row_major> fb;
                wmma::load_matrix_sync(fb, &Bs2[k0][wn * 64 + j * 16], PBS_LD);
                wmma::mma_sync(fc[j], fa, fb, fc[j]);
            }
        }
        __syncthreads();
        #pragma unroll
        for (int j = 0; j < 4; ++j)
            wmma::store_matrix_sync(&C2[wm * 16][wn * 64 + j * 16], fc[j], PCS_LD,
                                    wmma::mem_row_major);
        __syncthreads();

        // e-vec for heads 2z, 2z+1
        {
            const int row = tid >> 2, q = tid & 3;
            #pragma unroll
            for (int hh = 0; hh < 2; ++hh) {
                const int hg = z * 2 + hh;
                float s1 = 0.f, s2 = 0.f;
                #pragma unroll
                for (int i = 0; i < 16; ++i) {
                    float v = C2[row][hh * 64 + q * 16 + i];
                    s1 = fmaf(v, a1[hg * Ff + q * 16 + i], s1);
                    s2 = fmaf(v, a2[hg * Ff + q * 16 + i], s2);
                }
                s1 += __shfl_xor_sync(0xffffffffu, s1, 1);
                s2 += __shfl_xor_sync(0xffffffffu, s2, 1);
                s1 += __shfl_xor_sync(0xffffffffu, s1, 2);
                s2 += __shfl_xor_sync(0xffffffffu, s2, 2);
                if (q == 0 && r0 + row < Nn) {
                    g_e1v[(rowB + r0 + row) * 4 + hg] = s1;
                    g_e2v[(rowB + r0 + row) * 4 + hg] = s2;
                }
            }
        }
        // Wh2 store
        __half2* dst = (__half2*)g_Wh16;
        #pragma unroll
        for (int k = 0; k < 16; ++k) {
            int idx = k * 256 + tid;
            int r = idx >> 6, p = idx & 63;
            if (r0 + r < Nn) {
                dst[(rowB + r0 + r) * (HF / 2) + z * 64 + p] =
                    __floats2half2_rn(C2[r][2 * p], C2[r][2 * p + 1]);
            }
        }
        __syncthreads();
    }
}

// ================= fusedB: mix2 -> h2 tile (smem only) -> final HMMA -> out =========
// grid (Ss, 8), block 256, 2 blocks/SM forced (reg cap 128).
#define FB_OFF_C 36864
#define FB_OFF_T (36864 + 17408)
#define FB_SMEM (FB_OFF_T + 27648)     // 81920
__global__ __launch_bounds__(256, 2)
void fusedB(const float* __restrict__ bias,
            const float* __restrict__ bm,
            const __half* __restrict__ x16,
            const __half* __restrict__ h1in,
            float* __restrict__ out) {
    extern __shared__ __align__(16) char fsm[];
    __half (*Bs1)[72] = (__half(*)[72])fsm;                  // 256x72 WgT
    __half (*FB)[72] = (__half(*)[72])fsm;                   // reuse: 192x72 final B
    float (*C1)[68] = (float(*)[68])(fsm + FB_OFF_C);
    __half (*Tl)[72] = (__half(*)[72])(fsm + FB_OFF_T);      // 192 rows: x | h1 | h2

    const int s = blockIdx.x;
    const int r0 = blockIdx.y * 64;
    const int tid = threadIdx.x;
    const int wid = tid >> 5;
    const int wm = wid & 3, wn = wid >> 2;
    const size_t rowB = (size_t)s * Nn;

    // stage Bs1 = WgT16 + x/h1 tiles
    {
        const uint4* src = (const uint4*)g_WgT16;
        #pragma unroll
        for (int k = 0; k < 8; ++k) {
            int idx = k * 256 + tid;
            int r = idx >> 3, p = idx & 7;
            *(uint4*)&Bs1[r][p * 8] = src[r * 8 + p];
        }
        const uint4* sx = (const uint4*)x16;
        const uint4* sh = (const uint4*)h1in;
        #pragma unroll
        for (int k = 0; k < 2; ++k) {
            int idx = k * 256 + tid;              // 512 = 64 rows x 8 uint4
            int r = idx >> 3, p = idx & 7;
            int row = r0 + r;
            uint4 vx = make_uint4(0, 0, 0, 0), vh = vx;
            if (row < Nn) {
                vx = sx[(rowB + row) * 8 + p];
                vh = sh[(rowB + row) * 8 + p];
            }
            *(uint4*)&Tl[r][p * 8] = vx;
            *(uint4*)&Tl[64 + r][p * 8] = vh;
        }
    }
    __syncthreads();

    // mix wmma (A global hpr2, B = Bs1)
    {
        const __half* Aslice = g_hpr16 + rowB * HF;
        wmma::fragment<wmma::accumulator, 16, 16, 16, float> fc[2];
        wmma::fill_fragment(fc[0], 0.f);
        wmma::fill_fragment(fc[1], 0.f);
        #pragma unroll
        for (int k0 = 0; k0 < HF; k0 += 16) {
            wmma::fragment<wmma::matrix_a, 16, 16, 16, __half, wmma::row_major> fa;
            wmma::load_matrix_sync(fa, Aslice + (size_t)(r0 + wm * 16) * HF + k0, HF);
            #pragma unroll
            for (int sub = 0; sub < 2; ++sub) {
                wmma::fragment<wmma::matrix_b, 16, 16, 16, __half, wmma::row_major> fb;
                wmma::load_matrix_sync(fb, &Bs1[k0][wn * 32 + sub * 16], 72);
                wmma::mma_sync(fc[sub], fa, fb, fc[sub]);
            }
        }
        __syncthreads();
        wmma::store_matrix_sync(&C1[wm * 16][wn * 32], fc[0], 68, wmma::mem_row_major);
        wmma::store_matrix_sync(&C1[wm * 16][wn * 32 + 16], fc[1], 68, wmma::mem_row_major);
    }
    __syncthreads();

    // epilogue: h2 tile (smem only) ; stage final B (overwrites Bs1)
    {
        #pragma unroll
        for (int k = 0; k < 8; ++k) {
            int idx = k * 256 + tid;
            int r = idx >> 5, pc = idx & 31;
            int row = r0 + r;
            float v0 = 0.f, v1 = 0.f;
            if (row < Nn) {
                float2 xv = __half22float2(*(const __half2*)&Tl[r][2 * pc]);
                v0 = ALPHAc * xv.x + OMAc * (C1[r][2 * pc]     + bias[2 * pc]);
                v1 = ALPHAc * xv.y + OMAc * (C1[r][2 * pc + 1] + bias[2 * pc + 1]);
            }
            *(__half2*)&Tl[128 + r][2 * pc] = __floats2half2_rn(v0, v1);
        }
        const uint4* src = (const uint4*)g_Wfin16;   // 192 rows x 8 uint4
        #pragma unroll
        for (int k = 0; k < 6; ++k) {
            int idx = k * 256 + tid;
            int r = idx >> 3, p = idx & 7;
            *(uint4*)&FB[r][p * 8] = src[r * 8 + p];
        }
    }
    __syncthreads();

    // final wmma: out = x@Wx + h1@W1 + h2@W2, K = 3x64
    {
        wmma::fragment<wmma::accumulator, 16, 16, 16, float> fc[2];
        wmma::fill_fragment(fc[0], 0.f);
        wmma::fill_fragment(fc[1], 0.f);
        #pragma unroll
        for (int t3 = 0; t3 < 3; ++t3) {
            #pragma unroll
            for (int k0 = 0; k0 < 64; k0 += 16) {
                wmma::fragment<wmma::matrix_a, 16, 16, 16, __half, wmma::row_major> fa;
                wmma::load_matrix_sync(fa, &Tl[t3 * 64 + wm * 16][k0], 72);
                #pragma unroll
                for (int sub = 0; sub < 2; ++sub) {
                    wmma::fragment<wmma::matrix_b, 16, 16, 16, __half, wmma::row_major> fb;
                    wmma::load_matrix_sync(fb, &FB[t3 * 64 + k0][wn * 32 + sub * 16], 72);
                    wmma::mma_sync(fc[sub], fa, fb, fc[sub]);
                }
            }
        }
        __syncthreads();
        wmma::store_matrix_sync(&C1[wm * 16][wn * 32], fc[0], 68, wmma::mem_row_major);
        wmma::store_matrix_sync(&C1[wm * 16][wn * 32 + 16], fc[1], 68, wmma::mem_row_major);
    }
    __syncthreads();

    // out epilogue: out[b,c,n,t]
    const int b = s / Tt, t = s % Tt;
    #pragma unroll
    for (int k = 0; k < 16; ++k) {
        int idx = k * 256 + tid;
        int r = idx >> 6, c = idx & 63;
        int row = r0 + r;
        if (row < Nn)
            out[(((size_t)b * Cc + c) * Nn + row) * Tt + t] = C1[r][c] + bm[c];
    }
}

// ---------------- launch ----------------
extern "C" void kernel_launch(void* const* d_in, const int* in_sizes, int n_in,
                              void* d_out, int out_size) {
    const float* x   = (const float*)d_in[0];
    const float* adj = (const float*)d_in[1];
    const float* W   = (const float*)d_in[2];
    const float* a1  = (const float*)d_in[3];
    const float* a2  = (const float*)d_in[4];
    const float* Wg  = (const float*)d_in[5];
    const float* bg  = (const float*)d_in[6];
    const float* Wm  = (const float*)d_in[7];
    const float* bm  = (const float*)d_in[8];
    float* out = (float*)d_out;

    __half *xT16, *h1T16;
    cudaGetSymbolAddress((void**)&xT16,  g_xT16);
    cudaGetSymbolAddress((void**)&h1T16, g_h1T16);

    static bool attr_set = false;
    if (!attr_set) {
        cudaFuncSetAttribute(fusedA, cudaFuncAttributeMaxDynamicSharedMemorySize, FA_SMEM);
        cudaFuncSetAttribute(fusedB, cudaFuncAttributeMaxDynamicSharedMemorySize, FB_SMEM);
        attr_set = true;
    }

    prep_all<<<1213, 256>>>(adj, W, Wg, Wm, x);
    gemm_proj16<<<dim3(Ss, 8, 2), 256>>>(xT16, a1, a2);
    attn_agg<<<dim3(Nn, Ss), 128>>>();
    fusedA<<<dim3(Ss, 8), 256, FA_SMEM>>>(bg, xT16, h1T16, a1, a2);
    attn_agg<<<dim3(Nn, Ss), 128>>>();
    fusedB<<<dim3(Ss, 8), 256, FB_SMEM>>>(bg, bm, xT16, h1T16, out);
}

// round 17
// speedup vs baseline: 1.6385x; 1.0693x over previous
#include <cuda_runtime.h>
#include <cuda_fp16.h>
#include <mma.h>
#include <cstdint>

using namespace nvcuda;

// Problem constants
#define Bb 8
#define Cc 64
#define Nn 500
#define Tt 12
#define Hh 4
#define Ff 64
#define Ss (Bb * Tt)   // 96 slices (b,t)
#define HF (Hh * Ff)   // 256
#define MAXD 128
#define ROWPAD 16
#define ALPHAc 0.05f
#define OMAc 0.95f
#define LEAKc 0.2f

// ---------------- scratch (device globals; no allocation) ----------------
__device__ __half  g_xT16[Ss * Nn * Cc];                 // [s,n,c] fp16
__device__ __half  g_h1T16[Ss * Nn * Cc];
__device__ __half  g_Wh16[(size_t)Ss * Nn * HF];         // [s,n,hf] fp16
__device__ __half  g_hpr16[((size_t)Ss * Nn + ROWPAD) * HF]; // padded for OOB rows
__device__ float   g_e1v[Ss * Nn * 4];                   // [(s*N+n)*4 + h]
__device__ float   g_e2v[Ss * Nn * 4];
__device__ __half  g_Wcat16[Cc * HF];                    // [c, h*F+f] fp16
__device__ __half  g_WgT16[HF * Cc];                     // [hf, o] fp16
__device__ __half  g_Wfin16[3 * Cc * Cc];                // 3 x [c][o] fp16 (Wm blocks^T)
__device__ int     g_cnt[Nn];
__device__ int     g_nbr[Nn * MAXD];

// ================= merged prep: nbr list + weight layouts + input transpose =========
__global__ void prep_all(const float* __restrict__ adj,
                         const float* __restrict__ W,
                         const float* __restrict__ Wg,
                         const float* __restrict__ Wm,
                         const float* __restrict__ x) {
    __shared__ float sm[16][193];
    const int blk = blockIdx.x;
    if (blk < 125) {
        if (threadIdx.x >= 128) return;
        int warp = threadIdx.x >> 5;
        int lane = threadIdx.x & 31;
        int n = blk * 4 + warp;
        if (n >= Nn) return;
        int base = 0;
        for (int m0 = 0; m0 < 512; m0 += 32) {
            int m = m0 + lane;
            bool p = (m < Nn) && (adj[n * Nn + m] > 0.f || m == n);
            unsigned mask = __ballot_sync(0xffffffffu, p);
            if (p) {
                int r = __popc(mask & ((1u << lane) - 1));
                if (base + r < MAXD) g_nbr[n * MAXD + base + r] = m;
            }
            base += __popc(mask);
        }
        if (lane == 0) g_cnt[n] = base < MAXD ? base : MAXD;
    } else if (blk < 189) {
        int i = (blk - 125) * 256 + threadIdx.x;
        if (i < Hh * Cc * Ff) {  // Wcat16[c, h*F+f] = W[h,c,f]
            int f = i % Ff; int rest = i / Ff;
            int c = rest % Cc; int h = rest / Cc;
            g_Wcat16[c * HF + h * Ff + f] = __float2half_rn(W[(h * Cc + c) * Ff + f]);
        }
        if (i < HF * Cc) {       // WgT16[hf, o] = half(Wg[o, hf])
            int o = i % Cc; int hf = i / Cc;
            g_WgT16[hf * Cc + o] = __float2half_rn(Wg[o * HF + hf]);
        }
        if (i < 3 * Cc * Cc) {   // Wfin16[wsel][c][o] = half(Wm[o][wsel*64 + c])
            int o = i % Cc; int cg = i / Cc;
            int wsel = cg >> 6, c = cg & 63;
            g_Wfin16[(wsel * Cc + c) * Cc + o] =
                __float2half_rn(Wm[o * (3 * Cc) + wsel * 64 + c]);
        }
    } else {
        // transpose: x[b,c,n,t] -> xT16[s,n,c]
        if (threadIdx.x >= 192) return;
        const int bi = blk - 189;
        const int nb = bi & 31, cb = (bi >> 5) & 3, b = bi >> 7;
        const int c0 = cb * 16, n0 = nb * 16;
        const int tt_ = threadIdx.x;
        const int ni_l = tt_ / 12, tl = tt_ % 12;
        const int n_l = n0 + ni_l;
        #pragma unroll
        for (int ci = 0; ci < 16; ++ci) {
            float v = 0.f;
            if (n_l < Nn)
                v = x[(((size_t)b * Cc + c0 + ci) * Nn + n_l) * Tt + tl];
            sm[ci][tt_] = v;
        }
        __syncthreads();
        #pragma unroll
        for (int rep = 0; rep < 16; ++rep) {
            int idx = rep * 192 + tt_;
            int ci = idx & 15;
            int rest = idx >> 4;
            int ni = rest / 12, t = rest % 12;
            int n = n0 + ni;
            if (n < Nn)
                g_xT16[(((size_t)(b * Tt + t) * Nn) + n) * Cc + c0 + ci] =
                    __float2half_rn(sm[ci][rest]);
        }
    }
}

// ================= fp16 HMMA projection GEMM (2 heads/block) + e-vec + fp16 Wh ======
#define PAS_LD 72
#define PBS_LD 136
#define PCS_LD 132
__global__ void gemm_proj16(const __half* __restrict__ Ain,
                            const float* __restrict__ a1,
                            const float* __restrict__ a2) {
    __shared__ __align__(16) char smemRaw[64 * PCS_LD * 4];      // 33792 B
    __half (*As)[PAS_LD] = (__half(*)[PAS_LD])smemRaw;           // 9216 B
    __half (*Bs)[PBS_LD] = (__half(*)[PBS_LD])(smemRaw + 64 * PAS_LD * 2); // 17408 B
    float (*Cs)[PCS_LD] = (float(*)[PCS_LD])smemRaw;             // reuse after MMA

    const int s = blockIdx.x;
    const int r0 = blockIdx.y * 64;
    const int z = blockIdx.z;            // head pair
    const int c0 = z * 128;
    const int tid = threadIdx.x;
    const int wid = tid >> 5;
    const int wm = wid & 3, wn = wid >> 2;   // rows wm*16, cols wn*64
    const size_t rowB = (size_t)s * Nn;

    {
        const uint4* srcA = (const uint4*)(Ain + rowB * Cc);
        #pragma unroll
        for (int k = 0; k < 2; ++k) {
            int idx = k * 256 + tid;
            int r = idx >> 3, p = idx & 7;
            int row = r0 + r;
            uint4 v = make_uint4(0, 0, 0, 0);
            if (row < Nn) v = srcA[(size_t)row * 8 + p];
            *(uint4*)&As[r][p * 8] = v;
        }
    }
    {
        const uint4* srcB = (const uint4*)(g_Wcat16 + c0);
        #pragma unroll
        for (int k = 0; k < 4; ++k) {
            int idx = k * 256 + tid;
            int r = idx >> 4, p = idx & 15;
            *(uint4*)&Bs[r][p * 8] = srcB[r * 32 + p];   // row stride 256 half = 32 uint4
        }
    }
    __syncthreads();

    wmma::fragment<wmma::accumulator, 16, 16, 16, float> fc[4];
    #pragma unroll
    for (int j = 0; j < 4; ++j) wmma::fill_fragment(fc[j], 0.f);
    #pragma unroll
    for (int k0 = 0; k0 < 64; k0 += 16) {
        wmma::fragment<wmma::matrix_a, 16, 16, 16, __half, wmma::row_major> fa;
        wmma::load_matrix_sync(fa, &As[wm * 16][k0], PAS_LD);
        #pragma unroll
        for (int j = 0; j < 4; ++j) {
            wmma::fragment<wmma::matrix_b, 16, 16, 16, __half, wmma::row_major> fb;
            wmma::load_matrix_sync(fb, &Bs[k0][wn * 64 + j * 16], PBS_LD);
            wmma::mma_sync(fc[j], fa, fb, fc[j]);
        }
    }
    __syncthreads();   // done reading As/Bs; reuse as Cs
    #pragma unroll
    for (int j = 0; j < 4; ++j)
        wmma::store_matrix_sync(&Cs[wm * 16][wn * 64 + j * 16], fc[j], PCS_LD,
                                wmma::mem_row_major);
    __syncthreads();

    // fused e-vec for both heads (interleaved [n][4] layout) -- fp32, exact logits
    {
        const int row = tid >> 2, q = tid & 3;
        #pragma unroll
        for (int hh = 0; hh < 2; ++hh) {
            const int hg = z * 2 + hh;           // global head
            float s1 = 0.f, s2 = 0.f;
            #pragma unroll
            for (int i = 0; i < 16; ++i) {
                int cl = hh * 64 + q * 16 + i;
                float v = Cs[row][cl];
                s1 = fmaf(v, a1[hg * Ff + q * 16 + i], s1);
                s2 = fmaf(v, a2[hg * Ff + q * 16 + i], s2);
            }
            s1 += __shfl_xor_sync(0xffffffffu, s1, 1);
            s2 += __shfl_xor_sync(0xffffffffu, s2, 1);
            s1 += __shfl_xor_sync(0xffffffffu, s1, 2);
            s2 += __shfl_xor_sync(0xffffffffu, s2, 2);
            if (q == 0 && r0 + row < Nn) {
                g_e1v[(rowB + r0 + row) * 4 + hg] = s1;
                g_e2v[(rowB + r0 + row) * 4 + hg] = s2;
            }
        }
    }

    // fp16 Wh store (coalesced): 64 rows x 64 half2
    __half2* dst = (__half2*)g_Wh16;
    #pragma unroll
    for (int k = 0; k < 16; ++k) {
        int idx = k * 256 + tid;
        int r = idx >> 6, p = idx & 63;
        if (r0 + r < Nn) {
            dst[(rowB + r0 + r) * (HF / 2) + z * 64 + p] =
                __floats2half2_rn(Cs[r][2 * p], Cs[r][2 * p + 1]);
        }
    }
}

// ---------------- attention (R10): block (n,s), 128 thr; HFMA2 gather ------
__global__ void attn_agg() {
    const int n = blockIdx.x, s = blockIdx.y;
    const int t = threadIdx.x;
    const int h = t >> 5, lane = t & 31;
    __shared__ int snbr[MAXD];
    __shared__ __half swh[Hh][MAXD];
    __shared__ __half2 sred[4][32][4];     // [gatherWarp][chunk][pair]

    const int cnt = min(g_cnt[n], MAXD);
    for (int j = t; j < cnt; j += 128) snbr[j] = g_nbr[n * MAXD + j];
    __syncthreads();

    const size_t rowB = (size_t)s * Nn;
    const float e1v = g_e1v[(rowB + n) * 4 + h];
    float ev[4];
    float mx = -1e30f;
    #pragma unroll
    for (int k = 0; k < 4; ++k) {
        int j = k * 32 + lane;
        float e = -1e30f;
        if (j < cnt) {
            float tv = e1v + g_e2v[(rowB + snbr[j]) * 4 + h];
            e = tv > 0.f ? tv : LEAKc * tv;
        }
        ev[k] = e;
        mx = fmaxf(mx, e);
    }
    #pragma unroll
    for (int o = 16; o; o >>= 1) mx = fmaxf(mx, __shfl_xor_sync(0xffffffffu, mx, o));
    float sum = 0.f;
    #pragma unroll
    for (int k = 0; k < 4; ++k) {
        float w = (k * 32 + lane < cnt) ? __expf(ev[k] - mx) : 0.f;
        ev[k] = w;
        sum += w;
    }
    #pragma unroll
    for (int o = 16; o; o >>= 1) sum += __shfl_xor_sync(0xffffffffu, sum, o);
    const float inv = 1.f / sum;
    #pragma unroll
    for (int k = 0; k < 4; ++k) {
        int j = k * 32 + lane;
        if (j < cnt) swh[h][j] = __float2half_rn(ev[k] * inv);
    }
    __syncthreads();

    const int g = t >> 5, c = t & 31;
    const int hc = c >> 3;
    const uint4* Whv = (const uint4*)g_Wh16;
    __half2 a0 = __float2half2_rn(0.f), a1h = a0, a2h = a0, a3h = a0;
    #pragma unroll 2
    for (int j0 = 0; j0 < cnt; j0 += 4) {
        int j = j0 + g;
        if (j < cnt) {
            int m = snbr[j];
            __half2 w2 = __half2half2(swh[hc][j]);
            uint4 v = Whv[(rowB + m) * 32 + c];
            a0 = __hfma2(*(__half2*)&v.x, w2, a0);
            a1h = __hfma2(*(__half2*)&v.y, w2, a1h);
            a2h = __hfma2(*(__half2*)&v.z, w2, a2h);
            a3h = __hfma2(*(__half2*)&v.w, w2, a3h);
        }
    }
    sred[g][c][0] = a0;
    sred[g][c][1] = a1h;
    sred[g][c][2] = a2h;
    sred[g][c][3] = a3h;
    __syncthreads();

    const int rc = t >> 2, rp = t & 3;
    float2 v0 = __half22float2(sred[0][rc][rp]);
    float2 v1 = __half22float2(sred[1][rc][rp]);
    float2 v2 = __half22float2(sred[2][rc][rp]);
    float2 v3 = __half22float2(sred[3][rc][rp]);
    float vx = v0.x + v1.x + v2.x + v3.x;
    float vy = v0.y + v1.y + v2.y + v3.y;
    vx = vx > 0.f ? vx : (__expf(vx) - 1.f);
    vy = vy > 0.f ? vy : (__expf(vy) - 1.f);
    ((__half2*)g_hpr16)[(rowB + n) * (HF / 2) + t] = __floats2half2_rn(vx, vy);
}

// ================= fusedA: mix1 -> h1 tile -> proj2 + e-vec ========================
// grid (Ss, 8), block 256, 2 blocks/SM. A(hpr) tile bulk-staged to smem.
// smem: At 64x264 (33792, reused as C1/C2) | Bs1 256x72 (36864, reused as Bs2) | Ht 9216
#define AT_LD 264
#define FA_OFF_B 33792
#define FA_OFF_H (33792 + 36864)
#define FA_SMEM (FA_OFF_H + 9216)      // 79872
__global__ __launch_bounds__(256, 2)
void fusedA(const float* __restrict__ bias,
            const __half* __restrict__ x16,
            __half* __restrict__ h1out,
            const float* __restrict__ a1,
            const float* __restrict__ a2) {
    extern __shared__ __align__(16) char fsm[];
    __half (*At)[AT_LD] = (__half(*)[AT_LD])fsm;             // hpr tile
    __half (*Bs1)[72] = (__half(*)[72])(fsm + FA_OFF_B);     // WgT
    __half (*Bs2)[PBS_LD] = (__half(*)[PBS_LD])(fsm + FA_OFF_B); // reuse: Wcat chunk
    float (*C1)[68] = (float(*)[68])fsm;                     // reuse At region
    float (*C2)[PCS_LD] = (float(*)[PCS_LD])fsm;             // reuse At region
    __half (*Ht)[72] = (__half(*)[72])(fsm + FA_OFF_H);

    const int s = blockIdx.x;
    const int r0 = blockIdx.y * 64;
    const int tid = threadIdx.x;
    const int wid = tid >> 5;
    const int wm = wid & 3, wn = wid >> 2;
    const size_t rowB = (size_t)s * Nn;

    // stage At (hpr tile, 64 rows x 32 uint4) + Bs1 (WgT, 256 rows x 8 uint4)
    {
        const uint4* srcA = (const uint4*)(g_hpr16);
        #pragma unroll
        for (int k = 0; k < 8; ++k) {
            int idx = k * 256 + tid;       // 2048
            int r = idx >> 5, p = idx & 31;
            int row = r0 + r;
            uint4 v = make_uint4(0, 0, 0, 0);
            if (row < Nn) v = srcA[(rowB + row) * 32 + p];
            *(uint4*)&At[r][p * 8] = v;
        }
        const uint4* src = (const uint4*)g_WgT16;
        #pragma unroll
        for (int k = 0; k < 8; ++k) {
            int idx = k * 256 + tid;
            int r = idx >> 3, p = idx & 7;
            *(uint4*)&Bs1[r][p * 8] = src[r * 8 + p];
        }
    }
    __syncthreads();

    // mix wmma: all-smem operands
    {
        wmma::fragment<wmma::accumulator, 16, 16, 16, float> fc[2];
        wmma::fill_fragment(fc[0], 0.f);
        wmma::fill_fragment(fc[1], 0.f);
        #pragma unroll
        for (int k0 = 0; k0 < HF; k0 += 16) {
            wmma::fragment<wmma::matrix_a, 16, 16, 16, __half, wmma::row_major> fa;
            wmma::load_matrix_sync(fa, &At[wm * 16][k0], AT_LD);
            #pragma unroll
            for (int sub = 0; sub < 2; ++sub) {
                wmma::fragment<wmma::matrix_b, 16, 16, 16, __half, wmma::row_major> fb;
                wmma::load_matrix_sync(fb, &Bs1[k0][wn * 32 + sub * 16], 72);
                wmma::mma_sync(fc[sub], fa, fb, fc[sub]);
            }
        }
        __syncthreads();   // done reading At/Bs1
        wmma::store_matrix_sync(&C1[wm * 16][wn * 32], fc[0], 68, wmma::mem_row_major);
        wmma::store_matrix_sync(&C1[wm * 16][wn * 32 + 16], fc[1], 68, wmma::mem_row_major);
    }
    __syncthreads();

    // epilogue: h1 = a*x + (1-a)*(C1 + bg); keep in Ht smem + write global h1out
    {
        const __half2* xs = (const __half2*)x16;
        __half2* dst = (__half2*)h1out;
        #pragma unroll
        for (int k = 0; k < 8; ++k) {
            int idx = k * 256 + tid;              // 2048 = 64 rows x 32 half2
            int r = idx >> 5, pc = idx & 31;
            int row = r0 + r;
            float v0 = 0.f, v1 = 0.f;
            if (row < Nn) {
                float2 xv = __half22float2(xs[(rowB + row) * 32 + pc]);
                v0 = ALPHAc * xv.x + OMAc * (C1[r][2 * pc]     + bias[2 * pc]);
                v1 = ALPHAc * xv.y + OMAc * (C1[r][2 * pc + 1] + bias[2 * pc + 1]);
            }
            __half2 hv = __floats2half2_rn(v0, v1);
            *(__half2*)&Ht[r][2 * pc] = hv;
            if (row < Nn) dst[(rowB + row) * 32 + pc] = hv;
        }
    }
    __syncthreads();

    // proj2: two head-pair chunks
    for (int z = 0; z < 2; ++z) {
        const int c0 = z * 128;
        {
            const uint4* srcW = (const uint4*)(g_Wcat16 + c0);
            #pragma unroll
            for (int k = 0; k < 4; ++k) {
                int idx = k * 256 + tid;
                int r = idx >> 4, p = idx & 15;
                *(uint4*)&Bs2[r][p * 8] = srcW[r * 32 + p];
            }
        }
        __syncthreads();
        wmma::fragment<wmma::accumulator, 16, 16, 16, float> fc[4];
        #pragma unroll
        for (int j = 0; j < 4; ++j) wmma::fill_fragment(fc[j], 0.f);
        #pragma unroll
        for (int k0 = 0; k0 < 64; k0 += 16) {
            wmma::fragment<wmma::matrix_a, 16, 16, 16, __half, wmma::row_major> fa;
            wmma::load_matrix_sync(fa, &Ht[wm * 16][k0], 72);
            #pragma unroll
            for (int j = 0; j < 4; ++j) {
                wmma::fragment<wmma::matrix_b, 16, 16, 16, __half, wmma::row_major> fb;
                wmma::load_matrix_sync(fb, &Bs2[k0][wn * 64 + j * 16], PBS_LD);
                wmma::mma_sync(fc[j], fa, fb, fc[j]);
            }
        }
        __syncthreads();
        #pragma unroll
        for (int j = 0; j < 4; ++j)
            wmma::store_matrix_sync(&C2[wm * 16][wn * 64 + j * 16], fc[j], PCS_LD,
                                    wmma::mem_row_major);
        __syncthreads();

        // e-vec for heads 2z, 2z+1
        {
            const int row = tid >> 2, q = tid & 3;
            #pragma unroll
            for (int hh = 0; hh < 2; ++hh) {
                const int hg = z * 2 + hh;
                float s1 = 0.f, s2 = 0.f;
                #pragma unroll
                for (int i = 0; i < 16; ++i) {
                    float v = C2[row][hh * 64 + q * 16 + i];
                    s1 = fmaf(v, a1[hg * Ff + q * 16 + i], s1);
                    s2 = fmaf(v, a2[hg * Ff + q * 16 + i], s2);
                }
                s1 += __shfl_xor_sync(0xffffffffu, s1, 1);
                s2 += __shfl_xor_sync(0xffffffffu, s2, 1);
                s1 += __shfl_xor_sync(0xffffffffu, s1, 2);
                s2 += __shfl_xor_sync(0xffffffffu, s2, 2);
                if (q == 0 && r0 + row < Nn) {
                    g_e1v[(rowB + r0 + row) * 4 + hg] = s1;
                    g_e2v[(rowB + r0 + row) * 4 + hg] = s2;
                }
            }
        }
        // Wh2 store
        __half2* dst = (__half2*)g_Wh16;
        #pragma unroll
        for (int k = 0; k < 16; ++k) {
            int idx = k * 256 + tid;
            int r = idx >> 6, p = idx & 63;
            if (r0 + r < Nn) {
                dst[(rowB + r0 + r) * (HF / 2) + z * 64 + p] =
                    __floats2half2_rn(C2[r][2 * p], C2[r][2 * p + 1]);
            }
        }
        __syncthreads();
    }
}

// ================= fusedB: mix2 -> h2 tile (smem only) -> final HMMA -> out =========
// grid (Ss, 8), block 256, 2 blocks/SM. A(hpr2) tile bulk-staged to smem.
// smem: At 33792 (reused C1) | Bs1 36864 (reused FB) | Tl 27648 = 98304
#define FB_OFF_B 33792
#define FB_OFF_T (33792 + 36864)
#define FB_SMEM (FB_OFF_T + 27648)     // 98304
__global__ __launch_bounds__(256, 2)
void fusedB(const float* __restrict__ bias,
            const float* __restrict__ bm,
            const __half* __restrict__ x16,
            const __half* __restrict__ h1in,
            float* __restrict__ out) {
    extern __shared__ __align__(16) char fsm[];
    __half (*At)[AT_LD] = (__half(*)[AT_LD])fsm;             // hpr2 tile
    __half (*Bs1)[72] = (__half(*)[72])(fsm + FB_OFF_B);     // WgT
    __half (*FB)[72] = (__half(*)[72])(fsm + FB_OFF_B);      // reuse: 192x72 final B
    float (*C1)[68] = (float(*)[68])fsm;                     // reuse At region
    __half (*Tl)[72] = (__half(*)[72])(fsm + FB_OFF_T);      // 192 rows: x | h1 | h2

    const int s = blockIdx.x;
    const int r0 = blockIdx.y * 64;
    const int tid = threadIdx.x;
    const int wid = tid >> 5;
    const int wm = wid & 3, wn = wid >> 2;
    const size_t rowB = (size_t)s * Nn;

    // stage At (hpr2) + Bs1 (WgT) + x/h1 tiles
    {
        const uint4* srcA = (const uint4*)(g_hpr16);
        #pragma unroll
        for (int k = 0; k < 8; ++k) {
            int idx = k * 256 + tid;
            int r = idx >> 5, p = idx & 31;
            int row = r0 + r;
            uint4 v = make_uint4(0, 0, 0, 0);
            if (row < Nn) v = srcA[(rowB + row) * 32 + p];
            *(uint4*)&At[r][p * 8] = v;
        }
        const uint4* src = (const uint4*)g_WgT16;
        #pragma unroll
        for (int k = 0; k < 8; ++k) {
            int idx = k * 256 + tid;
            int r = idx >> 3, p = idx & 7;
            *(uint4*)&Bs1[r][p * 8] = src[r * 8 + p];
        }
        const uint4* sx = (const uint4*)x16;
        const uint4* sh = (const uint4*)h1in;
        #pragma unroll
        for (int k = 0; k < 2; ++k) {
            int idx = k * 256 + tid;              // 512 = 64 rows x 8 uint4
            int r = idx >> 3, p = idx & 7;
            int row = r0 + r;
            uint4 vx = make_uint4(0, 0, 0, 0), vh = vx;
            if (row < Nn) {
                vx = sx[(rowB + row) * 8 + p];
                vh = sh[(rowB + row) * 8 + p];
            }
            *(uint4*)&Tl[r][p * 8] = vx;
            *(uint4*)&Tl[64 + r][p * 8] = vh;
        }
    }
    __syncthreads();

    // mix wmma (all-smem operands)
    {
        wmma::fragment<wmma::accumulator, 16, 16, 16, float> fc[2];
        wmma::fill_fragment(fc[0], 0.f);
        wmma::fill_fragment(fc[1], 0.f);
        #pragma unroll
        for (int k0 = 0; k0 < HF; k0 += 16) {
            wmma::fragment<wmma::matrix_a, 16, 16, 16, __half, wmma::row_major> fa;
            wmma::load_matrix_sync(fa, &At[wm * 16][k0], AT_LD);
            #pragma unroll
            for (int sub = 0; sub < 2; ++sub) {
                wmma::fragment<wmma::matrix_b, 16, 16, 16, __half, wmma::row_major> fb;
                wmma::load_matrix_sync(fb, &Bs1[k0][wn * 32 + sub * 16], 72);
                wmma::mma_sync(fc[sub], fa, fb, fc[sub]);
            }
        }
        __syncthreads();   // done reading At/Bs1
        wmma::store_matrix_sync(&C1[wm * 16][wn * 32], fc[0], 68, wmma::mem_row_major);
        wmma::store_matrix_sync(&C1[wm * 16][wn * 32 + 16], fc[1], 68, wmma::mem_row_major);
    }
    __syncthreads();

    // epilogue: h2 tile (smem only) ; stage final B (overwrites Bs1)
    {
        #pragma unroll
        for (int k = 0; k < 8; ++k) {
            int idx = k * 256 + tid;
            int r = idx >> 5, pc = idx & 31;
            int row = r0 + r;
            float v0 = 0.f, v1 = 0.f;
            if (row < Nn) {
                float2 xv = __half22float2(*(const __half2*)&Tl[r][2 * pc]);
                v0 = ALPHAc * xv.x + OMAc * (C1[r][2 * pc]     + bias[2 * pc]);
                v1 = ALPHAc * xv.y + OMAc * (C1[r][2 * pc + 1] + bias[2 * pc + 1]);
            }
            *(__half2*)&Tl[128 + r][2 * pc] = __floats2half2_rn(v0, v1);
        }
        const uint4* src = (const uint4*)g_Wfin16;   // 192 rows x 8 uint4
        #pragma unroll
        for (int k = 0; k < 6; ++k) {
            int idx = k * 256 + tid;
            int r = idx >> 3, p = idx & 7;
            *(uint4*)&FB[r][p * 8] = src[r * 8 + p];
        }
    }
    __syncthreads();

    // final wmma: out = x@Wx + h1@W1 + h2@W2, K = 3x64
    {
        wmma::fragment<wmma::accumulator, 16, 16, 16, float> fc[2];
        wmma::fill_fragment(fc[0], 0.f);
        wmma::fill_fragment(fc[1], 0.f);
        #pragma unroll
        for (int t3 = 0; t3 < 3; ++t3) {
            #pragma unroll
            for (int k0 = 0; k0 < 64; k0 += 16) {
                wmma::fragment<wmma::matrix_a, 16, 16, 16, __half, wmma::row_major> fa;
                wmma::load_matrix_sync(fa, &Tl[t3 * 64 + wm * 16][k0], 72);
                #pragma unroll
                for (int sub = 0; sub < 2; ++sub) {
                    wmma::fragment<wmma::matrix_b, 16, 16, 16, __half, wmma::row_major> fb;
                    wmma::load_matrix_sync(fb, &FB[t3 * 64 + k0][wn * 32 + sub * 16], 72);
                    wmma::mma_sync(fc[sub], fa, fb, fc[sub]);
                }
            }
        }
        __syncthreads();
        wmma::store_matrix_sync(&C1[wm * 16][wn * 32], fc[0], 68, wmma::mem_row_major);
        wmma::store_matrix_sync(&C1[wm * 16][wn * 32 + 16], fc[1], 68, wmma::mem_row_major);
    }
    __syncthreads();

    // out epilogue: out[b,c,n,t]
    const int b = s / Tt, t = s % Tt;
    #pragma unroll
    for (int k = 0; k < 16; ++k) {
        int idx = k * 256 + tid;
        int r = idx >> 6, c = idx & 63;
        int row = r0 + r;
        if (row < Nn)
            out[(((size_t)b * Cc + c) * Nn + row) * Tt + t] = C1[r][c] + bm[c];
    }
}

// ---------------- launch ----------------
extern "C" void kernel_launch(void* const* d_in, const int* in_sizes, int n_in,
                              void* d_out, int out_size) {
    const float* x   = (const float*)d_in[0];
    const float* adj = (const float*)d_in[1];
    const float* W   = (const float*)d_in[2];
    const float* a1  = (const float*)d_in[3];
    const float* a2  = (const float*)d_in[4];
    const float* Wg  = (const float*)d_in[5];
    const float* bg  = (const float*)d_in[6];
    const float* Wm  = (const float*)d_in[7];
    const float* bm  = (const float*)d_in[8];
    float* out = (float*)d_out;

    __half *xT16, *h1T16;
    cudaGetSymbolAddress((void**)&xT16,  g_xT16);
    cudaGetSymbolAddress((void**)&h1T16, g_h1T16);

    static bool attr_set = false;
    if (!attr_set) {
        cudaFuncSetAttribute(fusedA, cudaFuncAttributeMaxDynamicSharedMemorySize, FA_SMEM);
        cudaFuncSetAttribute(fusedB, cudaFuncAttributeMaxDynamicSharedMemorySize, FB_SMEM);
        attr_set = true;
    }

    prep_all<<<1213, 256>>>(adj, W, Wg, Wm, x);
    gemm_proj16<<<dim3(Ss, 8, 2), 256>>>(xT16, a1, a2);
    attn_agg<<<dim3(Nn, Ss), 128>>>();
    fusedA<<<dim3(Ss, 8), 256, FA_SMEM>>>(bg, xT16, h1T16, a1, a2);
    attn_agg<<<dim3(Nn, Ss), 128>>>();
    fusedB<<<dim3(Ss, 8), 256, FB_SMEM>>>(bg, bm, xT16, h1T16, out);
}